// round 1
// baseline (speedup 1.0000x reference)
#include <cuda_runtime.h>

#define NTOK 16384
#define DIM  1024
#define NH   16
#define HD   64

// Scratch: 0..8 = Q1,K1,V1,Q2,K2,V2,Q3,K3,V3 projections; 9 = averaged attention out.
__device__ float g_buf[10][(size_t)NTOK * DIM];

// ---------------------------------------------------------------------------
// C = A @ W^T + bias  (optionally ReLU).  A:[M,K] row-major, W:[N,K] row-major.
// M = NTOK, N = K = DIM. 128x128 tile, K-slice 8, 256 threads, 8x8 microtile.
// ---------------------------------------------------------------------------
__global__ __launch_bounds__(256, 2)
void sgemm_nt(const float* __restrict__ Ain, const float* __restrict__ W,
              const float* __restrict__ bias, float* __restrict__ Cout,
              int aIdx, int cIdx, int do_relu)
{
    const float* A = Ain  ? Ain  : g_buf[aIdx];
    float*       C = Cout ? Cout : g_buf[cIdx];

    __shared__ float As[8][128];
    __shared__ float Bs[8][128];

    const int K  = DIM;
    const int NN = DIM;
    const int row0 = blockIdx.y * 128;
    const int col0 = blockIdx.x * 128;
    const int tid = threadIdx.x;

    // Loader mapping: 2 threads per tile row, each loads a float4 of K.
    const int lr = tid >> 1;          // 0..127 row within tile
    const int lc = (tid & 1) << 2;    // 0 or 4 within the 8-wide K slice
    // Compute mapping: 16x16 thread grid of 8x8 microtiles.
    const int ty = tid >> 4;          // 0..15
    const int tx = tid & 15;          // 0..15

    float acc[8][8];
    #pragma unroll
    for (int i = 0; i < 8; i++)
        #pragma unroll
        for (int j = 0; j < 8; j++) acc[i][j] = 0.f;

    const float* Aptr = A + (size_t)(row0 + lr) * K + lc;
    const float* Wptr = W + (size_t)(col0 + lr) * K + lc;

    for (int k0 = 0; k0 < K; k0 += 8) {
        float4 a4 = *(const float4*)(Aptr + k0);
        float4 b4 = *(const float4*)(Wptr + k0);
        As[lc + 0][lr] = a4.x; As[lc + 1][lr] = a4.y;
        As[lc + 2][lr] = a4.z; As[lc + 3][lr] = a4.w;
        Bs[lc + 0][lr] = b4.x; Bs[lc + 1][lr] = b4.y;
        Bs[lc + 2][lr] = b4.z; Bs[lc + 3][lr] = b4.w;
        __syncthreads();

        #pragma unroll
        for (int k = 0; k < 8; k++) {
            float4 a0 = *(const float4*)&As[k][ty * 8];
            float4 a1 = *(const float4*)&As[k][ty * 8 + 4];
            float4 b0 = *(const float4*)&Bs[k][tx * 8];
            float4 b1 = *(const float4*)&Bs[k][tx * 8 + 4];
            float ar[8] = {a0.x, a0.y, a0.z, a0.w, a1.x, a1.y, a1.z, a1.w};
            float br[8] = {b0.x, b0.y, b0.z, b0.w, b1.x, b1.y, b1.z, b1.w};
            #pragma unroll
            for (int i = 0; i < 8; i++)
                #pragma unroll
                for (int j = 0; j < 8; j++)
                    acc[i][j] += ar[i] * br[j];
        }
        __syncthreads();
    }

    #pragma unroll
    for (int i = 0; i < 8; i++) {
        const int r = row0 + ty * 8 + i;
        #pragma unroll
        for (int j = 0; j < 8; j += 4) {
            const int c = col0 + tx * 8 + j;
            float4 v;
            v.x = acc[i][j + 0] + bias[c + 0];
            v.y = acc[i][j + 1] + bias[c + 1];
            v.z = acc[i][j + 2] + bias[c + 2];
            v.w = acc[i][j + 3] + bias[c + 3];
            if (do_relu) {
                v.x = fmaxf(v.x, 0.f); v.y = fmaxf(v.y, 0.f);
                v.z = fmaxf(v.z, 0.f); v.w = fmaxf(v.w, 0.f);
            }
            *(float4*)&C[(size_t)r * NN + c] = v;
        }
    }
}

// ---------------------------------------------------------------------------
// Per-token attention x3 + average.
// Layout: projection row x[n][h*64+d] == Q[d][h] (after reshape+transpose).
// scores[d][e] = (1/8) sum_h Q[d,h]K[e,h]; softmax over d (axis=1!);
// o[d][h] = sum_e w[d,e] V[e,h]; out[n][h*64+d] = mean of 3 attentions.
// One CTA per token, 128 threads.
// ---------------------------------------------------------------------------
__global__ __launch_bounds__(128)
void attn_kernel()
{
    __shared__ float Qs[DIM], Ks[DIM], Vs[DIM];
    __shared__ float S[64 * 65];   // S[e*65 + d] = scores[d][e]; pad 65 avoids bank conflicts

    const int n = blockIdx.x;
    const int t = threadIdx.x;

    float acc[8];
    #pragma unroll
    for (int r = 0; r < 8; r++) acc[r] = 0.f;

    for (int a = 0; a < 3; a++) {
        const float* Qp = g_buf[3 * a + 0] + (size_t)n * DIM;
        const float* Kp = g_buf[3 * a + 1] + (size_t)n * DIM;
        const float* Vp = g_buf[3 * a + 2] + (size_t)n * DIM;

        for (int i = t; i < DIM; i += 128) {
            Qs[i] = Qp[i];
            Ks[i] = Kp[i];
            Vs[i] = Vp[i];
        }
        __syncthreads();

        // scores
        for (int idx = t; idx < 64 * 64; idx += 128) {
            const int e = idx >> 6, d = idx & 63;
            float s = 0.f;
            #pragma unroll
            for (int h = 0; h < NH; h++)
                s += Qs[h * 64 + d] * Ks[h * 64 + e];
            S[e * 65 + d] = s * 0.125f;   // 1/sqrt(64)
        }
        __syncthreads();

        // softmax over d for each column e
        if (t < 64) {
            const int e = t;
            float m = -1e30f;
            #pragma unroll 4
            for (int d = 0; d < 64; d++) m = fmaxf(m, S[e * 65 + d]);
            float sum = 0.f;
            #pragma unroll 4
            for (int d = 0; d < 64; d++) {
                float ex = __expf(S[e * 65 + d] - m);
                S[e * 65 + d] = ex;
                sum += ex;
            }
            const float inv = 1.f / sum;
            #pragma unroll 4
            for (int d = 0; d < 64; d++) S[e * 65 + d] *= inv;
        }
        __syncthreads();

        // o[d][h] accumulate: thread t owns (h,d) pairs idx = t + r*128, d = t&63 fixed
        #pragma unroll
        for (int r = 0; r < 8; r++) {
            const int idx = t + r * 128;
            const int h = idx >> 6, d = idx & 63;
            float o = 0.f;
            #pragma unroll
            for (int e = 0; e < 64; e++)
                o += S[e * 65 + d] * Vs[h * 64 + e];
            acc[r] += o;
        }
        __syncthreads();   // S/Qs/Ks/Vs reused next iteration
    }

    float* Op = g_buf[9] + (size_t)n * DIM;
    #pragma unroll
    for (int r = 0; r < 8; r++)
        Op[t + r * 128] = acc[r] * (1.f / 3.f);
}

// ---------------------------------------------------------------------------
extern "C" void kernel_launch(void* const* d_in, const int* in_sizes, int n_in,
                              void* d_out, int out_size)
{
    (void)in_sizes; (void)n_in; (void)out_size;
    const float* q = (const float*)d_in[0];
    const float* k = (const float*)d_in[1];
    const float* v = (const float*)d_in[2];

    // d_in: 3 Wq1,4 bq1,5 Wk1,6 bk1,7 Wv1,8 bv1,9 Wq2,10 bq2,11 Wk2,12 bk2,
    //       13 Wv2,14 bv2,15 Wq3,16 bq3,17 Wk3,18 bk3,19 Wv3,20 bv3,21 Wo,22 bo
    // Cross-wired per reference:
    //   buf0 Q1 = query @ Wq1 ; buf1 K1 = value @ Wk2 ; buf2 V1 = key   @ Wv1
    //   buf3 Q2 = value @ Wq2 ; buf4 K2 = key   @ Wk1 ; buf5 V2 = query @ Wv2
    //   buf6 Q3 = key   @ Wq3 ; buf7 K3 = query @ Wk3 ; buf8 V3 = value @ Wv3
    struct Map { const float* A; int w; };
    const Map maps[9] = {
        {q, 3}, {v, 11}, {k, 7},
        {v, 9}, {k, 5},  {q, 13},
        {k, 15}, {q, 17}, {v, 19}
    };

    dim3 grid(DIM / 128, NTOK / 128);
    for (int i = 0; i < 9; i++) {
        sgemm_nt<<<grid, 256>>>(maps[i].A,
                                (const float*)d_in[maps[i].w],
                                (const float*)d_in[maps[i].w + 1],
                                nullptr, 0, i, 0);
    }

    attn_kernel<<<NTOK, 128>>>();

    sgemm_nt<<<grid, 256>>>(nullptr,
                            (const float*)d_in[21],
                            (const float*)d_in[22],
                            (float*)d_out, 9, 0, 1);
}

// round 3
// speedup vs baseline: 2.1051x; 2.1051x over previous
#include <cuda_runtime.h>
#include <cuda_bf16.h>
#include <cstdint>

#define NTOK 16384
#define DIM  1024
#define NH   16

// ---------------- scratch (allocation-free __device__ globals) ----------------
__device__ float g_proj[9][(size_t)NTOK * DIM];                 // fp32 projections
__device__ __nv_bfloat16 g_in_hi[3][(size_t)NTOK * DIM];        // q,k,v hi (row-major)
__device__ __nv_bfloat16 g_in_lo[3][(size_t)NTOK * DIM];
__device__ __nv_bfloat16 g_avg_hi[(size_t)NTOK * DIM];          // averaged attn out
__device__ __nv_bfloat16 g_avg_lo[(size_t)NTOK * DIM];
__device__ __nv_bfloat16 g_w_hi[10][(size_t)DIM * DIM];         // weights (row-major [N,K])
__device__ __nv_bfloat16 g_w_lo[10][(size_t)DIM * DIM];

__device__ __forceinline__ uint32_t smem_u32(const void* p) {
    uint32_t a;
    asm("{ .reg .u64 t; cvta.to.shared.u64 t, %1; cvt.u32.u64 %0, t; }" : "=r"(a) : "l"(p));
    return a;
}

// ---------------- decompose fp32 -> (hi, lo) bf16, row-major ----------------
__global__ void decompose_k(const float* __restrict__ src, int is_w, int sel, int rows)
{
    size_t i = (size_t)blockIdx.x * blockDim.x + threadIdx.x;   // one thread = 2 cols
    if (i >= (size_t)rows * 512) return;
    size_t off = i * 2;

    float2 x = *(const float2*)(src + off);
    __nv_bfloat16 h0 = __float2bfloat16(x.x);
    __nv_bfloat16 h1 = __float2bfloat16(x.y);
    __nv_bfloat16 l0 = __float2bfloat16(x.x - __bfloat162float(h0));
    __nv_bfloat16 l1 = __float2bfloat16(x.y - __bfloat162float(h1));

    __nv_bfloat16* H = is_w ? g_w_hi[sel] : g_in_hi[sel];
    __nv_bfloat16* L = is_w ? g_w_lo[sel] : g_in_lo[sel];
    __nv_bfloat162 hv; hv.x = h0; hv.y = h1;
    __nv_bfloat162 lv; lv.x = l0; lv.y = l1;
    *(__nv_bfloat162*)(H + off) = hv;
    *(__nv_bfloat162*)(L + off) = lv;
}

// ---------------- mma.sync bf16 split GEMM: C = A @ W^T + bias (opt ReLU) --------
// A:[M,1024] row-major bf16 (hi/lo), W:[1024,1024] row-major bf16 (hi/lo).
// Block 128x128, BK=32, 256 threads (8 warps, 2x4), warp tile 64x32.
// 3 passes over K: hi*hi, hi*lo, lo*hi -> 96 chunks, cp.async double-buffered.

#define BK 32
#define ROWB 80                 // smem row stride in bytes (64 data + 16 pad)
#define BUFB (128 * ROWB)       // 10240 bytes per tile buffer

__global__ __launch_bounds__(256, 2)
void gemm_mma(int a_sel, int w_sel, const float* __restrict__ bias,
              float* __restrict__ outp, int out_sel, int do_relu)
{
    __shared__ __align__(16) char sA[2 * BUFB];
    __shared__ __align__(16) char sB[2 * BUFB];

    const int tid = threadIdx.x;
    const int wid = tid >> 5;
    const int lane = tid & 31;
    const int bx = blockIdx.x;          // N block (0..7)
    const int by = blockIdx.y;          // M block (0..127)

    const __nv_bfloat16* Ahi = (a_sel < 3) ? g_in_hi[a_sel] : g_avg_hi;
    const __nv_bfloat16* Alo = (a_sel < 3) ? g_in_lo[a_sel] : g_avg_lo;
    const __nv_bfloat16* Bhi = g_w_hi[w_sel];
    const __nv_bfloat16* Blo = g_w_lo[w_sel];
    float* C = outp ? outp : g_proj[out_sel];

    const uint32_t sAu = smem_u32(sA);
    const uint32_t sBu = smem_u32(sB);

    // loader: idx in [0,512): row = idx>>2, 16B segment = idx&3 (two idx per thread)
    const int ldr0 = tid >> 2, lds0 = tid & 3;
    const int ldr1 = (tid + 256) >> 2, lds1 = tid & 3;
    const size_t gA0 = (size_t)(by * 128 + ldr0) * DIM + lds0 * 8;
    const size_t gA1 = (size_t)(by * 128 + ldr1) * DIM + lds1 * 8;
    const size_t gB0 = (size_t)(bx * 128 + ldr0) * DIM + lds0 * 8;
    const size_t gB1 = (size_t)(bx * 128 + ldr1) * DIM + lds1 * 8;
    const uint32_t smA0 = sAu + ldr0 * ROWB + lds0 * 16;
    const uint32_t smA1 = sAu + ldr1 * ROWB + lds1 * 16;
    const uint32_t smB0 = sBu + ldr0 * ROWB + lds0 * 16;
    const uint32_t smB1 = sBu + ldr1 * ROWB + lds1 * 16;

    // warp tiling
    const int warp_m = (wid >> 2) * 64;
    const int warp_n = (wid & 3) * 32;
    const int quad = lane >> 3, l7 = lane & 7;
    // A ldmatrix lane offsets: row = (quad&1)*8 + l7, kbyte = (quad>>1)*16
    const uint32_t aoff = (uint32_t)((warp_m + (quad & 1) * 8 + l7) * ROWB + (quad >> 1) * 16);
    // B ldmatrix lane offsets: row(n) = (quad>>1)*8 + l7, kbyte = (quad&1)*16
    const uint32_t boff = (uint32_t)((warp_n + (quad >> 1) * 8 + l7) * ROWB + (quad & 1) * 16);

    float acc[4][4][4];
    #pragma unroll
    for (int i = 0; i < 4; i++)
        #pragma unroll
        for (int j = 0; j < 4; j++)
            #pragma unroll
            for (int r = 0; r < 4; r++) acc[i][j][r] = 0.f;

    const int NC = 96;   // 3 passes * 32 chunks

    auto issue_chunk = [&](int c, int buf) {
        const int p = c >> 5;
        const int ko = (c & 31) << 5;
        const __nv_bfloat16* Ag = (p < 2) ? Ahi : Alo;
        const __nv_bfloat16* Bg = (p == 1) ? Blo : Bhi;
        const uint32_t bo = buf * BUFB;
        asm volatile("cp.async.cg.shared.global [%0], [%1], 16;" :: "r"(smA0 + bo), "l"(Ag + gA0 + ko));
        asm volatile("cp.async.cg.shared.global [%0], [%1], 16;" :: "r"(smA1 + bo), "l"(Ag + gA1 + ko));
        asm volatile("cp.async.cg.shared.global [%0], [%1], 16;" :: "r"(smB0 + bo), "l"(Bg + gB0 + ko));
        asm volatile("cp.async.cg.shared.global [%0], [%1], 16;" :: "r"(smB1 + bo), "l"(Bg + gB1 + ko));
        asm volatile("cp.async.commit_group;");
    };

    issue_chunk(0, 0);

    for (int c = 0; c < NC; c++) {
        const int cur = c & 1;
        if (c + 1 < NC) issue_chunk(c + 1, cur ^ 1);
        if (c + 1 < NC) asm volatile("cp.async.wait_group 1;");
        else            asm volatile("cp.async.wait_group 0;");
        __syncthreads();

        const uint32_t abase = sAu + cur * BUFB;  (void)abase;
        const uint32_t aL = aoff + cur * BUFB;
        const uint32_t bL = boff + cur * BUFB;

        #pragma unroll
        for (int ks = 0; ks < 2; ks++) {
            uint32_t af[4][4];
            #pragma unroll
            for (int mt = 0; mt < 4; mt++) {
                uint32_t addr = sAu + aL + mt * (16 * ROWB) + ks * 32;
                asm volatile("ldmatrix.sync.aligned.m8n8.x4.shared.b16 {%0,%1,%2,%3}, [%4];"
                             : "=r"(af[mt][0]), "=r"(af[mt][1]), "=r"(af[mt][2]), "=r"(af[mt][3])
                             : "r"(addr));
            }
            uint32_t bf[2][4];
            #pragma unroll
            for (int nt = 0; nt < 2; nt++) {
                uint32_t addr = sBu + bL + nt * (16 * ROWB) + ks * 32;
                asm volatile("ldmatrix.sync.aligned.m8n8.x4.shared.b16 {%0,%1,%2,%3}, [%4];"
                             : "=r"(bf[nt][0]), "=r"(bf[nt][1]), "=r"(bf[nt][2]), "=r"(bf[nt][3])
                             : "r"(addr));
            }
            #pragma unroll
            for (int mt = 0; mt < 4; mt++) {
                #pragma unroll
                for (int n8 = 0; n8 < 4; n8++) {
                    uint32_t b0 = bf[n8 >> 1][(n8 & 1) * 2 + 0];
                    uint32_t b1 = bf[n8 >> 1][(n8 & 1) * 2 + 1];
                    asm volatile(
                        "mma.sync.aligned.m16n8k16.row.col.f32.bf16.bf16.f32 "
                        "{%0,%1,%2,%3}, {%4,%5,%6,%7}, {%8,%9}, {%0,%1,%2,%3};"
                        : "+f"(acc[mt][n8][0]), "+f"(acc[mt][n8][1]),
                          "+f"(acc[mt][n8][2]), "+f"(acc[mt][n8][3])
                        : "r"(af[mt][0]), "r"(af[mt][1]), "r"(af[mt][2]), "r"(af[mt][3]),
                          "r"(b0), "r"(b1));
                }
            }
        }
        __syncthreads();
    }

    // epilogue
    const int erow0 = by * 128 + warp_m + (lane >> 2);
    const int ecol0 = bx * 128 + warp_n + 2 * (lane & 3);
    #pragma unroll
    for (int mt = 0; mt < 4; mt++) {
        #pragma unroll
        for (int n8 = 0; n8 < 4; n8++) {
            const int col = ecol0 + n8 * 8;
            const float b0 = bias[col], b1 = bias[col + 1];
            #pragma unroll
            for (int h = 0; h < 2; h++) {   // h=0: row, h=1: row+8
                const int row = erow0 + mt * 16 + h * 8;
                float2 v;
                v.x = acc[mt][n8][2 * h + 0] + b0;
                v.y = acc[mt][n8][2 * h + 1] + b1;
                if (do_relu) { v.x = fmaxf(v.x, 0.f); v.y = fmaxf(v.y, 0.f); }
                *(float2*)(C + (size_t)row * DIM + col) = v;
            }
        }
    }
}

// ---------------- per-token attention x3 + average (writes row-major hi/lo) ------
__global__ __launch_bounds__(128)
void attn_kernel()
{
    __shared__ float Qs[DIM], Ks[DIM], Vs[DIM];
    __shared__ float S[64 * 65];   // S[e*65+d]

    const int n = blockIdx.x;
    const int t = threadIdx.x;

    float acc[8];
    #pragma unroll
    for (int r = 0; r < 8; r++) acc[r] = 0.f;

    for (int a = 0; a < 3; a++) {
        const float* Qp = g_proj[3 * a + 0] + (size_t)n * DIM;
        const float* Kp = g_proj[3 * a + 1] + (size_t)n * DIM;
        const float* Vp = g_proj[3 * a + 2] + (size_t)n * DIM;

        for (int i = t; i < DIM; i += 128) {
            Qs[i] = Qp[i];
            Ks[i] = Kp[i];
            Vs[i] = Vp[i];
        }
        __syncthreads();

        for (int idx = t; idx < 64 * 64; idx += 128) {
            const int e = idx >> 6, d = idx & 63;
            float s = 0.f;
            #pragma unroll
            for (int h = 0; h < NH; h++)
                s += Qs[h * 64 + d] * Ks[h * 64 + e];
            S[e * 65 + d] = s * 0.125f;
        }
        __syncthreads();

        if (t < 64) {
            const int e = t;
            float m = -1e30f;
            #pragma unroll 4
            for (int d = 0; d < 64; d++) m = fmaxf(m, S[e * 65 + d]);
            float sum = 0.f;
            #pragma unroll 4
            for (int d = 0; d < 64; d++) {
                float ex = __expf(S[e * 65 + d] - m);
                S[e * 65 + d] = ex;
                sum += ex;
            }
            const float inv = 1.f / sum;
            #pragma unroll 4
            for (int d = 0; d < 64; d++) S[e * 65 + d] *= inv;
        }
        __syncthreads();

        #pragma unroll
        for (int r = 0; r < 8; r++) {
            const int idx = t + r * 128;
            const int h = idx >> 6, d = idx & 63;
            float o = 0.f;
            #pragma unroll
            for (int e = 0; e < 64; e++)
                o += S[e * 65 + d] * Vs[h * 64 + e];
            acc[r] += o;
        }
        __syncthreads();
    }

    size_t base = (size_t)n * DIM;
    #pragma unroll
    for (int r = 0; r < 8; r++) {
        float v = acc[r] * (1.f / 3.f);
        __nv_bfloat16 hi = __float2bfloat16(v);
        __nv_bfloat16 lo = __float2bfloat16(v - __bfloat162float(hi));
        g_avg_hi[base + t + r * 128] = hi;
        g_avg_lo[base + t + r * 128] = lo;
    }
}

// ---------------------------------------------------------------------------
extern "C" void kernel_launch(void* const* d_in, const int* in_sizes, int n_in,
                              void* d_out, int out_size)
{
    (void)in_sizes; (void)n_in; (void)out_size;

    // decompose inputs q,k,v
    for (int s = 0; s < 3; s++)
        decompose_k<<<NTOK * 2, 256>>>((const float*)d_in[s], 0, s, NTOK);
    // decompose weights: d_in[3 + 2j] -> g_w[j], j = 0..9
    for (int j = 0; j < 10; j++)
        decompose_k<<<DIM * 2, 256>>>((const float*)d_in[3 + 2 * j], 1, j, DIM);

    // projections (cross-wired per reference):
    // buf0 Q1=q@Wq1(3)  buf1 K1=v@Wk2(11) buf2 V1=k@Wv1(7)
    // buf3 Q2=v@Wq2(9)  buf4 K2=k@Wk1(5)  buf5 V2=q@Wv2(13)
    // buf6 Q3=k@Wq3(15) buf7 K3=q@Wk3(17) buf8 V3=v@Wv3(19)
    const int amap[9] = {0, 2, 1, 2, 1, 0, 1, 0, 2};
    const int wmap[9] = {3, 11, 7, 9, 5, 13, 15, 17, 19};

    dim3 grid(8, 128);
    for (int i = 0; i < 9; i++) {
        int j = (wmap[i] - 3) / 2;
        gemm_mma<<<grid, 256>>>(amap[i], j,
                                (const float*)d_in[wmap[i] + 1],
                                nullptr, i, 0);
    }

    attn_kernel<<<NTOK, 128>>>();

    // final: out = relu(avg @ Wo^T + bo)
    gemm_mma<<<grid, 256>>>(3, 9, (const float*)d_in[22],
                            (float*)d_out, 0, 1);
}

// round 4
// speedup vs baseline: 3.2396x; 1.5389x over previous
#include <cuda_runtime.h>
#include <cuda_fp16.h>
#include <cstdint>

#define NTOK 16384
#define DIM  1024
#define NH   16

// ---------------- scratch (allocation-free __device__ globals) ----------------
__device__ float g_proj[9][(size_t)NTOK * DIM];          // fp32 projections
__device__ __half g_in_hi[3][(size_t)NTOK * DIM];        // q,k,v hi (row-major)
__device__ __half g_in_lo[3][(size_t)NTOK * DIM];
__device__ __half g_avg_hi[(size_t)NTOK * DIM];          // averaged attn out
__device__ __half g_avg_lo[(size_t)NTOK * DIM];
__device__ __half g_w_hi[10][(size_t)DIM * DIM];         // weights hi only (row-major [N,K])

__device__ __forceinline__ uint32_t smem_u32(const void* p) {
    uint32_t a;
    asm("{ .reg .u64 t; cvta.to.shared.u64 t, %1; cvt.u32.u64 %0, t; }" : "=r"(a) : "l"(p));
    return a;
}

// ---------------- fused decompose: all 13 tensors in ONE launch ----------------
// inputs (q,k,v): fp32 -> hi+lo fp16 ; weights: fp32 -> hi fp16 only.
#define IN2 ((size_t)NTOK * 512)    // float2 count per input tensor
#define W2  ((size_t)DIM * 512)     // float2 count per weight tensor

__global__ void decompose_all(
    const float* __restrict__ q, const float* __restrict__ k, const float* __restrict__ v,
    const float* __restrict__ w0, const float* __restrict__ w1, const float* __restrict__ w2,
    const float* __restrict__ w3, const float* __restrict__ w4, const float* __restrict__ w5,
    const float* __restrict__ w6, const float* __restrict__ w7, const float* __restrict__ w8,
    const float* __restrict__ w9)
{
    size_t i = (size_t)blockIdx.x * blockDim.x + threadIdx.x;
    const size_t NIN = 3 * IN2;
    if (i < NIN) {
        int sel = (int)(i / IN2);
        size_t off = (i - (size_t)sel * IN2) * 2;
        const float* src = (sel == 0) ? q : (sel == 1) ? k : v;
        float2 x = *(const float2*)(src + off);
        __half h0 = __float2half_rn(x.x);
        __half h1 = __float2half_rn(x.y);
        __half l0 = __float2half_rn(x.x - __half2float(h0));
        __half l1 = __float2half_rn(x.y - __half2float(h1));
        __half2 hv; hv.x = h0; hv.y = h1;
        __half2 lv; lv.x = l0; lv.y = l1;
        *(__half2*)(g_in_hi[sel] + off) = hv;
        *(__half2*)(g_in_lo[sel] + off) = lv;
    } else {
        size_t j = i - NIN;
        if (j >= 10 * W2) return;
        int sel = (int)(j / W2);
        size_t off = (j - (size_t)sel * W2) * 2;
        const float* ws[10] = {w0, w1, w2, w3, w4, w5, w6, w7, w8, w9};
        const float* src = ws[sel];
        float2 x = *(const float2*)(src + off);
        __half2 hv;
        hv.x = __float2half_rn(x.x);
        hv.y = __float2half_rn(x.y);
        *(__half2*)(g_w_hi[sel] + off) = hv;
    }
}

// ---------------- mma.sync fp16 2-pass GEMM: C = A @ W^T + bias (opt ReLU) -------
// Block 128x128, BK=32, 256 threads (8 warps 2x4), warp tile 64x32.
// Per k-chunk: load A_hi, A_lo, B(hi) ; compute acc += A_hi*B + A_lo*B.
// 3-stage cp.async pipeline, one __syncthreads per chunk.

#define ROWB 80                   // smem row stride bytes (64 data + 16 pad)
#define TILEB (128 * ROWB)        // 10240 bytes per tile
#define STAGEB (3 * TILEB)        // A_hi, A_lo, B per stage
#define NSTAGE 3
#define DYN_SMEM (NSTAGE * STAGEB)
#define NC 32

__global__ __launch_bounds__(256, 2)
void gemm_mma(int a_sel, int w_sel, const float* __restrict__ bias,
              float* __restrict__ outp, int out_sel, int do_relu)
{
    extern __shared__ __align__(16) char dsm[];

    const int tid = threadIdx.x;
    const int wid = tid >> 5;
    const int lane = tid & 31;
    const int bx = blockIdx.x;          // N block (0..7)
    const int by = blockIdx.y;          // M block (0..127)

    const __half* Ahi = (a_sel < 3) ? g_in_hi[a_sel] : g_avg_hi;
    const __half* Alo = (a_sel < 3) ? g_in_lo[a_sel] : g_avg_lo;
    const __half* Bhi = g_w_hi[w_sel];
    float* C = outp ? outp : g_proj[out_sel];

    const uint32_t smu = smem_u32(dsm);

    // loader: 512 16B-segments per tile, 2 per thread. row = idx>>2, seg = idx&3
    const int ldr0 = tid >> 2, lds = tid & 3;
    const int ldr1 = (tid + 256) >> 2;
    const size_t gA0 = (size_t)(by * 128 + ldr0) * DIM + lds * 8;
    const size_t gA1 = (size_t)(by * 128 + ldr1) * DIM + lds * 8;
    const size_t gB0 = (size_t)(bx * 128 + ldr0) * DIM + lds * 8;
    const size_t gB1 = (size_t)(bx * 128 + ldr1) * DIM + lds * 8;
    const uint32_t so0 = (uint32_t)(ldr0 * ROWB + lds * 16);
    const uint32_t so1 = (uint32_t)(ldr1 * ROWB + lds * 16);

    // warp tiling
    const int warp_m = (wid >> 2) * 64;
    const int warp_n = (wid & 3) * 32;
    const int quad = lane >> 3, l7 = lane & 7;
    const uint32_t aoff = (uint32_t)((warp_m + (quad & 1) * 8 + l7) * ROWB + (quad >> 1) * 16);
    const uint32_t boff = (uint32_t)((warp_n + (quad >> 1) * 8 + l7) * ROWB + (quad & 1) * 16);

    float acc[4][4][4];
    #pragma unroll
    for (int i = 0; i < 4; i++)
        #pragma unroll
        for (int j = 0; j < 4; j++)
            #pragma unroll
            for (int r = 0; r < 4; r++) acc[i][j][r] = 0.f;

    auto issue_chunk = [&](int c, int stg) {
        const int ko = c << 5;                       // k offset in elements
        const uint32_t sb = smu + stg * STAGEB;
        asm volatile("cp.async.cg.shared.global [%0], [%1], 16;" :: "r"(sb + so0),              "l"(Ahi + gA0 + ko));
        asm volatile("cp.async.cg.shared.global [%0], [%1], 16;" :: "r"(sb + so1),              "l"(Ahi + gA1 + ko));
        asm volatile("cp.async.cg.shared.global [%0], [%1], 16;" :: "r"(sb + TILEB + so0),      "l"(Alo + gA0 + ko));
        asm volatile("cp.async.cg.shared.global [%0], [%1], 16;" :: "r"(sb + TILEB + so1),      "l"(Alo + gA1 + ko));
        asm volatile("cp.async.cg.shared.global [%0], [%1], 16;" :: "r"(sb + 2 * TILEB + so0),  "l"(Bhi + gB0 + ko));
        asm volatile("cp.async.cg.shared.global [%0], [%1], 16;" :: "r"(sb + 2 * TILEB + so1),  "l"(Bhi + gB1 + ko));
        asm volatile("cp.async.commit_group;");
    };

    issue_chunk(0, 0);
    issue_chunk(1, 1);

    int stg = 0;
    for (int c = 0; c < NC; c++) {
        if (c < NC - 1) asm volatile("cp.async.wait_group 1;");
        else            asm volatile("cp.async.wait_group 0;");
        __syncthreads();

        if (c + 2 < NC) {
            int nstg = stg + 2; if (nstg >= NSTAGE) nstg -= NSTAGE;
            issue_chunk(c + 2, nstg);
        }

        const uint32_t sb = smu + stg * STAGEB;
        #pragma unroll
        for (int ks = 0; ks < 2; ks++) {
            uint32_t bf[2][4];
            #pragma unroll
            for (int nt = 0; nt < 2; nt++) {
                uint32_t addr = sb + 2 * TILEB + boff + nt * (16 * ROWB) + ks * 32;
                asm volatile("ldmatrix.sync.aligned.m8n8.x4.shared.b16 {%0,%1,%2,%3}, [%4];"
                             : "=r"(bf[nt][0]), "=r"(bf[nt][1]), "=r"(bf[nt][2]), "=r"(bf[nt][3])
                             : "r"(addr));
            }
            uint32_t af[4][4];
            // pass 0: A_hi
            #pragma unroll
            for (int mt = 0; mt < 4; mt++) {
                uint32_t addr = sb + aoff + mt * (16 * ROWB) + ks * 32;
                asm volatile("ldmatrix.sync.aligned.m8n8.x4.shared.b16 {%0,%1,%2,%3}, [%4];"
                             : "=r"(af[mt][0]), "=r"(af[mt][1]), "=r"(af[mt][2]), "=r"(af[mt][3])
                             : "r"(addr));
            }
            #pragma unroll
            for (int mt = 0; mt < 4; mt++)
                #pragma unroll
                for (int n8 = 0; n8 < 4; n8++) {
                    uint32_t b0 = bf[n8 >> 1][(n8 & 1) * 2 + 0];
                    uint32_t b1 = bf[n8 >> 1][(n8 & 1) * 2 + 1];
                    asm volatile(
                        "mma.sync.aligned.m16n8k16.row.col.f32.f16.f16.f32 "
                        "{%0,%1,%2,%3}, {%4,%5,%6,%7}, {%8,%9}, {%0,%1,%2,%3};"
                        : "+f"(acc[mt][n8][0]), "+f"(acc[mt][n8][1]),
                          "+f"(acc[mt][n8][2]), "+f"(acc[mt][n8][3])
                        : "r"(af[mt][0]), "r"(af[mt][1]), "r"(af[mt][2]), "r"(af[mt][3]),
                          "r"(b0), "r"(b1));
                }
            // pass 1: A_lo (same B fragments)
            #pragma unroll
            for (int mt = 0; mt < 4; mt++) {
                uint32_t addr = sb + TILEB + aoff + mt * (16 * ROWB) + ks * 32;
                asm volatile("ldmatrix.sync.aligned.m8n8.x4.shared.b16 {%0,%1,%2,%3}, [%4];"
                             : "=r"(af[mt][0]), "=r"(af[mt][1]), "=r"(af[mt][2]), "=r"(af[mt][3])
                             : "r"(addr));
            }
            #pragma unroll
            for (int mt = 0; mt < 4; mt++)
                #pragma unroll
                for (int n8 = 0; n8 < 4; n8++) {
                    uint32_t b0 = bf[n8 >> 1][(n8 & 1) * 2 + 0];
                    uint32_t b1 = bf[n8 >> 1][(n8 & 1) * 2 + 1];
                    asm volatile(
                        "mma.sync.aligned.m16n8k16.row.col.f32.f16.f16.f32 "
                        "{%0,%1,%2,%3}, {%4,%5,%6,%7}, {%8,%9}, {%0,%1,%2,%3};"
                        : "+f"(acc[mt][n8][0]), "+f"(acc[mt][n8][1]),
                          "+f"(acc[mt][n8][2]), "+f"(acc[mt][n8][3])
                        : "r"(af[mt][0]), "r"(af[mt][1]), "r"(af[mt][2]), "r"(af[mt][3]),
                          "r"(b0), "r"(b1));
                }
        }
        stg++; if (stg >= NSTAGE) stg = 0;
    }

    // epilogue
    const int erow0 = by * 128 + warp_m + (lane >> 2);
    const int ecol0 = bx * 128 + warp_n + 2 * (lane & 3);
    #pragma unroll
    for (int mt = 0; mt < 4; mt++) {
        #pragma unroll
        for (int n8 = 0; n8 < 4; n8++) {
            const int col = ecol0 + n8 * 8;
            const float b0 = bias[col], b1 = bias[col + 1];
            #pragma unroll
            for (int h = 0; h < 2; h++) {
                const int row = erow0 + mt * 16 + h * 8;
                float2 v;
                v.x = acc[mt][n8][2 * h + 0] + b0;
                v.y = acc[mt][n8][2 * h + 1] + b1;
                if (do_relu) { v.x = fmaxf(v.x, 0.f); v.y = fmaxf(v.y, 0.f); }
                *(float2*)(C + (size_t)row * DIM + col) = v;
            }
        }
    }
}

// ---------------- per-token attention x3 + average (writes fp16 hi/lo) ------------
__global__ __launch_bounds__(128)
void attn_kernel()
{
    __shared__ float Qs[DIM], Ks[DIM], Vs[DIM];
    __shared__ float S[64 * 65];   // S[e*65+d]

    const int n = blockIdx.x;
    const int t = threadIdx.x;

    float acc[8];
    #pragma unroll
    for (int r = 0; r < 8; r++) acc[r] = 0.f;

    for (int a = 0; a < 3; a++) {
        const float* Qp = g_proj[3 * a + 0] + (size_t)n * DIM;
        const float* Kp = g_proj[3 * a + 1] + (size_t)n * DIM;
        const float* Vp = g_proj[3 * a + 2] + (size_t)n * DIM;

        for (int i = t; i < DIM; i += 128) {
            Qs[i] = Qp[i];
            Ks[i] = Kp[i];
            Vs[i] = Vp[i];
        }
        __syncthreads();

        for (int idx = t; idx < 64 * 64; idx += 128) {
            const int e = idx >> 6, d = idx & 63;
            float s = 0.f;
            #pragma unroll
            for (int h = 0; h < NH; h++)
                s += Qs[h * 64 + d] * Ks[h * 64 + e];
            S[e * 65 + d] = s * 0.125f;
        }
        __syncthreads();

        if (t < 64) {
            const int e = t;
            float m = -1e30f;
            #pragma unroll 4
            for (int d = 0; d < 64; d++) m = fmaxf(m, S[e * 65 + d]);
            float sum = 0.f;
            #pragma unroll 4
            for (int d = 0; d < 64; d++) {
                float ex = __expf(S[e * 65 + d] - m);
                S[e * 65 + d] = ex;
                sum += ex;
            }
            const float inv = 1.f / sum;
            #pragma unroll 4
            for (int d = 0; d < 64; d++) S[e * 65 + d] *= inv;
        }
        __syncthreads();

        #pragma unroll
        for (int r = 0; r < 8; r++) {
            const int idx = t + r * 128;
            const int h = idx >> 6, d = idx & 63;
            float o = 0.f;
            #pragma unroll
            for (int e = 0; e < 64; e++)
                o += S[e * 65 + d] * Vs[h * 64 + e];
            acc[r] += o;
        }
        __syncthreads();
    }

    size_t base = (size_t)n * DIM;
    #pragma unroll
    for (int r = 0; r < 8; r++) {
        float v = acc[r] * (1.f / 3.f);
        __half hi = __float2half_rn(v);
        __half lo = __float2half_rn(v - __half2float(hi));
        g_avg_hi[base + t + r * 128] = hi;
        g_avg_lo[base + t + r * 128] = lo;
    }
}

// ---------------------------------------------------------------------------
extern "C" void kernel_launch(void* const* d_in, const int* in_sizes, int n_in,
                              void* d_out, int out_size)
{
    (void)in_sizes; (void)n_in; (void)out_size;

    cudaFuncSetAttribute(gemm_mma, cudaFuncAttributeMaxDynamicSharedMemorySize, DYN_SMEM);

    // 1 fused decompose launch (also aligns ncu -s 5 onto a GEMM)
    {
        const size_t total = 3 * IN2 + 10 * W2;
        const int blocks = (int)((total + 255) / 256);
        decompose_all<<<blocks, 256>>>(
            (const float*)d_in[0], (const float*)d_in[1], (const float*)d_in[2],
            (const float*)d_in[3], (const float*)d_in[5], (const float*)d_in[7],
            (const float*)d_in[9], (const float*)d_in[11], (const float*)d_in[13],
            (const float*)d_in[15], (const float*)d_in[17], (const float*)d_in[19],
            (const float*)d_in[21]);
    }

    // projections (cross-wired per reference):
    // buf0 Q1=q@Wq1(w0)  buf1 K1=v@Wk2(w4) buf2 V1=k@Wv1(w2)
    // buf3 Q2=v@Wq2(w3)  buf4 K2=k@Wk1(w1) buf5 V2=q@Wv2(w5)
    // buf6 Q3=k@Wq3(w6)  buf7 K3=q@Wk3(w7) buf8 V3=v@Wv3(w8)
    const int amap[9] = {0, 2, 1, 2, 1, 0, 1, 0, 2};
    const int wmap[9] = {0, 4, 2, 3, 1, 5, 6, 7, 8};   // index into g_w (order of d_in 3,5,..)
    const int bmap[9] = {4, 12, 8, 10, 6, 14, 16, 18, 20};

    dim3 grid(8, 128);
    for (int i = 0; i < 9; i++) {
        gemm_mma<<<grid, 256, DYN_SMEM>>>(amap[i], wmap[i],
                                          (const float*)d_in[bmap[i]],
                                          nullptr, i, 0);
    }

    attn_kernel<<<NTOK, 128>>>();

    // final: out = relu(avg @ Wo^T + bo)   (Wo = g_w[9], bo = d_in[22])
    gemm_mma<<<grid, 256, DYN_SMEM>>>(3, 9, (const float*)d_in[22],
                                      (float*)d_out, 0, 1);
}

// round 6
// speedup vs baseline: 3.5765x; 1.1040x over previous
#include <cuda_runtime.h>
#include <cuda_fp16.h>
#include <cstdint>

#define NTOK 16384
#define DIM  1024
#define NH   16

// ---------------- scratch (allocation-free __device__ globals) ----------------
__device__ float g_proj[9][(size_t)NTOK * DIM];          // fp32 projections
__device__ __half g_in_hi[3][(size_t)NTOK * DIM];        // q,k,v hi (row-major)
__device__ __half g_in_lo[3][(size_t)NTOK * DIM];
__device__ __half g_avg_hi[(size_t)NTOK * DIM];          // averaged attn out
__device__ __half g_avg_lo[(size_t)NTOK * DIM];
__device__ __half g_w_hi[10][(size_t)DIM * DIM];         // weights hi (row-major [N,K])

__device__ __forceinline__ uint32_t smem_u32(const void* p) {
    uint32_t a;
    asm("{ .reg .u64 t; cvta.to.shared.u64 t, %1; cvt.u32.u64 %0, t; }" : "=r"(a) : "l"(p));
    return a;
}

// ---------------- fused decompose: all 13 tensors in ONE launch ----------------
#define IN2 ((size_t)NTOK * 512)    // float2 count per input tensor
#define W2  ((size_t)DIM * 512)     // float2 count per weight tensor

__global__ void decompose_all(
    const float* __restrict__ q, const float* __restrict__ k, const float* __restrict__ v,
    const float* __restrict__ w0, const float* __restrict__ w1, const float* __restrict__ w2,
    const float* __restrict__ w3, const float* __restrict__ w4, const float* __restrict__ w5,
    const float* __restrict__ w6, const float* __restrict__ w7, const float* __restrict__ w8,
    const float* __restrict__ w9)
{
    size_t i = (size_t)blockIdx.x * blockDim.x + threadIdx.x;
    const size_t NIN = 3 * IN2;
    if (i < NIN) {
        int sel = (int)(i / IN2);
        size_t off = (i - (size_t)sel * IN2) * 2;
        const float* src = (sel == 0) ? q : (sel == 1) ? k : v;
        float2 x = *(const float2*)(src + off);
        __half h0 = __float2half_rn(x.x);
        __half h1 = __float2half_rn(x.y);
        __half l0 = __float2half_rn(x.x - __half2float(h0));
        __half l1 = __float2half_rn(x.y - __half2float(h1));
        __half2 hv; hv.x = h0; hv.y = h1;
        __half2 lv; lv.x = l0; lv.y = l1;
        *(__half2*)(g_in_hi[sel] + off) = hv;
        *(__half2*)(g_in_lo[sel] + off) = lv;
    } else {
        size_t j = i - NIN;
        if (j >= 10 * W2) return;
        int sel = (int)(j / W2);
        size_t off = (j - (size_t)sel * W2) * 2;
        const float* ws[10] = {w0, w1, w2, w3, w4, w5, w6, w7, w8, w9};
        float2 x = *(const float2*)(ws[sel] + off);
        __half2 hv;
        hv.x = __float2half_rn(x.x);
        hv.y = __float2half_rn(x.y);
        *(__half2*)(g_w_hi[sel] + off) = hv;
    }
}

// ---------------- fp16 2-pass HMMA GEMM, BK=64, 2-stage ----------------
// C = A @ W^T + bias (opt ReLU). Up to 3 kilo-blocks in N (weight/bias/out per kb).
// a_sel: 0..2 = g_in[q/k/v], 3 = g_avg.  osel >= 0 -> g_proj[osel], else dext.
#define ROWB 144                    // 128B data + 16B pad
#define TILEB (128 * ROWB)          // 18432 B
#define STAGEB (3 * TILEB)          // A_hi, A_lo, B
#define DYN_SMEM (2 * STAGEB)       // 110592 B
#define NC 16

__global__ __launch_bounds__(256, 2)
void gemm_mma(int a_sel,
              int w0, int w1, int w2,
              const float* __restrict__ b0p, const float* __restrict__ b1p, const float* __restrict__ b2p,
              int o0, int o1, int o2, float* __restrict__ dext, int do_relu)
{
    extern __shared__ __align__(16) char dsm[];

    const int tid = threadIdx.x;
    const int wid = tid >> 5;
    const int lane = tid & 31;
    const int kb = blockIdx.x >> 3;     // kilo-block in N
    const int xb = blockIdx.x & 7;      // 128-col block within kilo-block
    const int by = blockIdx.y;          // M block

    const __half* Ahi = (a_sel < 3) ? g_in_hi[a_sel] : g_avg_hi;
    const __half* Alo = (a_sel < 3) ? g_in_lo[a_sel] : g_avg_lo;
    const int wsel = (kb == 0) ? w0 : (kb == 1) ? w1 : w2;
    const float* bias = (kb == 0) ? b0p : (kb == 1) ? b1p : b2p;
    const int osel = (kb == 0) ? o0 : (kb == 1) ? o1 : o2;
    const __half* Bhi = g_w_hi[wsel];
    float* C = (osel >= 0) ? g_proj[osel] : dext;

    const uint32_t smu = smem_u32(dsm);

    // loader: per tile 4 segs/thread; rows (tid>>3)+{0,32,64,96}, 16B seg tid&7
    const int lr = tid >> 3;
    const int lseg = (tid & 7) * 8;     // element offset within 64
    size_t gA[4], gB[4];
    uint32_t sOff[4];
    #pragma unroll
    for (int j = 0; j < 4; j++) {
        int r = lr + j * 32;
        gA[j] = (size_t)(by * 128 + r) * DIM + lseg;
        gB[j] = (size_t)(xb * 128 + r) * DIM + lseg;
        sOff[j] = (uint32_t)(r * ROWB + (tid & 7) * 16);
    }

    // warp tiling: 8 warps 2x4, warp tile 64x32
    const int warp_m = (wid >> 2) * 64;
    const int warp_n = (wid & 3) * 32;
    const int quad = lane >> 3, l7 = lane & 7;
    const uint32_t aoff = (uint32_t)((warp_m + (quad & 1) * 8 + l7) * ROWB + (quad >> 1) * 16);
    const uint32_t boff = (uint32_t)((warp_n + (quad >> 1) * 8 + l7) * ROWB + (quad & 1) * 16);

    float acc[4][4][4];
    #pragma unroll
    for (int i = 0; i < 4; i++)
        #pragma unroll
        for (int j = 0; j < 4; j++)
            #pragma unroll
            for (int r = 0; r < 4; r++) acc[i][j][r] = 0.f;

    auto issue_chunk = [&](int c, int stg) {
        const int ko = c << 6;                        // 64 elements per chunk
        const uint32_t sb = smu + stg * STAGEB;
        #pragma unroll
        for (int j = 0; j < 4; j++) {
            asm volatile("cp.async.cg.shared.global [%0], [%1], 16;"
                         :: "r"(sb + sOff[j]), "l"(Ahi + gA[j] + ko));
            asm volatile("cp.async.cg.shared.global [%0], [%1], 16;"
                         :: "r"(sb + TILEB + sOff[j]), "l"(Alo + gA[j] + ko));
            asm volatile("cp.async.cg.shared.global [%0], [%1], 16;"
                         :: "r"(sb + 2 * TILEB + sOff[j]), "l"(Bhi + gB[j] + ko));
        }
        asm volatile("cp.async.commit_group;");
    };

    issue_chunk(0, 0);

    for (int c = 0; c < NC; c++) {
        asm volatile("cp.async.wait_group 0;");
        __syncthreads();
        if (c + 1 < NC) issue_chunk(c + 1, (c + 1) & 1);

        const uint32_t sb = smu + (c & 1) * STAGEB;
        #pragma unroll
        for (int ks = 0; ks < 4; ks++) {
            uint32_t bf[2][4];
            #pragma unroll
            for (int nt = 0; nt < 2; nt++) {
                uint32_t addr = sb + 2 * TILEB + boff + nt * (16 * ROWB) + ks * 32;
                asm volatile("ldmatrix.sync.aligned.m8n8.x4.shared.b16 {%0,%1,%2,%3}, [%4];"
                             : "=r"(bf[nt][0]), "=r"(bf[nt][1]), "=r"(bf[nt][2]), "=r"(bf[nt][3])
                             : "r"(addr));
            }
            uint32_t af[4][4];
            #pragma unroll
            for (int mt = 0; mt < 4; mt++) {
                uint32_t addr = sb + aoff + mt * (16 * ROWB) + ks * 32;
                asm volatile("ldmatrix.sync.aligned.m8n8.x4.shared.b16 {%0,%1,%2,%3}, [%4];"
                             : "=r"(af[mt][0]), "=r"(af[mt][1]), "=r"(af[mt][2]), "=r"(af[mt][3])
                             : "r"(addr));
            }
            #pragma unroll
            for (int mt = 0; mt < 4; mt++)
                #pragma unroll
                for (int n8 = 0; n8 < 4; n8++) {
                    uint32_t bb0 = bf[n8 >> 1][(n8 & 1) * 2 + 0];
                    uint32_t bb1 = bf[n8 >> 1][(n8 & 1) * 2 + 1];
                    asm volatile(
                        "mma.sync.aligned.m16n8k16.row.col.f32.f16.f16.f32 "
                        "{%0,%1,%2,%3}, {%4,%5,%6,%7}, {%8,%9}, {%0,%1,%2,%3};"
                        : "+f"(acc[mt][n8][0]), "+f"(acc[mt][n8][1]),
                          "+f"(acc[mt][n8][2]), "+f"(acc[mt][n8][3])
                        : "r"(af[mt][0]), "r"(af[mt][1]), "r"(af[mt][2]), "r"(af[mt][3]),
                          "r"(bb0), "r"(bb1));
                }
            // A_lo pass (reuse B fragments)
            #pragma unroll
            for (int mt = 0; mt < 4; mt++) {
                uint32_t addr = sb + TILEB + aoff + mt * (16 * ROWB) + ks * 32;
                asm volatile("ldmatrix.sync.aligned.m8n8.x4.shared.b16 {%0,%1,%2,%3}, [%4];"
                             : "=r"(af[mt][0]), "=r"(af[mt][1]), "=r"(af[mt][2]), "=r"(af[mt][3])
                             : "r"(addr));
            }
            #pragma unroll
            for (int mt = 0; mt < 4; mt++)
                #pragma unroll
                for (int n8 = 0; n8 < 4; n8++) {
                    uint32_t bb0 = bf[n8 >> 1][(n8 & 1) * 2 + 0];
                    uint32_t bb1 = bf[n8 >> 1][(n8 & 1) * 2 + 1];
                    asm volatile(
                        "mma.sync.aligned.m16n8k16.row.col.f32.f16.f16.f32 "
                        "{%0,%1,%2,%3}, {%4,%5,%6,%7}, {%8,%9}, {%0,%1,%2,%3};"
                        : "+f"(acc[mt][n8][0]), "+f"(acc[mt][n8][1]),
                          "+f"(acc[mt][n8][2]), "+f"(acc[mt][n8][3])
                        : "r"(af[mt][0]), "r"(af[mt][1]), "r"(af[mt][2]), "r"(af[mt][3]),
                          "r"(bb0), "r"(bb1));
                }
        }
    }

    // epilogue
    const int erow0 = by * 128 + warp_m + (lane >> 2);
    const int ecol0 = xb * 128 + warp_n + 2 * (lane & 3);
    #pragma unroll
    for (int mt = 0; mt < 4; mt++) {
        #pragma unroll
        for (int n8 = 0; n8 < 4; n8++) {
            const int col = ecol0 + n8 * 8;
            const float bb0 = bias[col], bb1 = bias[col + 1];
            #pragma unroll
            for (int h = 0; h < 2; h++) {
                const int row = erow0 + mt * 16 + h * 8;
                float2 v;
                v.x = acc[mt][n8][2 * h + 0] + bb0;
                v.y = acc[mt][n8][2 * h + 1] + bb1;
                if (do_relu) { v.x = fmaxf(v.x, 0.f); v.y = fmaxf(v.y, 0.f); }
                *(float2*)(C + (size_t)row * DIM + col) = v;
            }
        }
    }
}

// ---------------- per-token attention x3 + average ----------------
__global__ __launch_bounds__(128)
void attn_kernel()
{
    __shared__ float Qs[DIM], Ks[DIM], Vs[DIM];
    __shared__ float S[64 * 65];     // S[e*65+d]
    __shared__ float red[128];       // softmax partials

    const int n = blockIdx.x;
    const int t = threadIdx.x;

    float acc[8];
    #pragma unroll
    for (int r = 0; r < 8; r++) acc[r] = 0.f;

    for (int a = 0; a < 3; a++) {
        const float4* Qp = (const float4*)(g_proj[3 * a + 0] + (size_t)n * DIM);
        const float4* Kp = (const float4*)(g_proj[3 * a + 1] + (size_t)n * DIM);
        const float4* Vp = (const float4*)(g_proj[3 * a + 2] + (size_t)n * DIM);
        #pragma unroll
        for (int j = 0; j < 2; j++) {
            int i = t + j * 128;
            ((float4*)Qs)[i] = Qp[i];
            ((float4*)Ks)[i] = Kp[i];
            ((float4*)Vs)[i] = Vp[i];
        }
        __syncthreads();

        // scores: S[e*65+d] = (1/8) sum_h Q[h*64+d] K[h*64+e]
        #pragma unroll
        for (int rr = 0; rr < 32; rr++) {
            int idx = t + rr * 128;
            const int e = idx >> 6, d = idx & 63;
            float s = 0.f;
            #pragma unroll
            for (int h = 0; h < NH; h++)
                s += Qs[h * 64 + d] * Ks[h * 64 + e];
            S[e * 65 + d] = s * 0.125f;
        }
        __syncthreads();

        // softmax over d, parallel: thread (e = t&63, half = t>>6) owns 32 d's
        {
            const int e = t & 63;
            const int d0 = (t >> 6) * 32;
            float m = -1e30f;
            #pragma unroll 8
            for (int d = 0; d < 32; d++) m = fmaxf(m, S[e * 65 + d0 + d]);
            red[t] = m;
            __syncthreads();
            m = fmaxf(red[e], red[e + 64]);
            __syncthreads();
            float sum = 0.f;
            #pragma unroll 8
            for (int d = 0; d < 32; d++) {
                float ex = __expf(S[e * 65 + d0 + d] - m);
                S[e * 65 + d0 + d] = ex;
                sum += ex;
            }
            red[t] = sum;
            __syncthreads();
            const float inv = 1.f / (red[e] + red[e + 64]);
            #pragma unroll 8
            for (int d = 0; d < 32; d++) S[e * 65 + d0 + d] *= inv;
        }
        __syncthreads();

        // o[d][h] accumulate
        #pragma unroll
        for (int r = 0; r < 8; r++) {
            const int idx = t + r * 128;
            const int h = idx >> 6, d = idx & 63;
            float o = 0.f;
            #pragma unroll
            for (int e = 0; e < 64; e++)
                o += S[e * 65 + d] * Vs[h * 64 + e];
            acc[r] += o;
        }
        __syncthreads();
    }

    size_t base = (size_t)n * DIM;
    #pragma unroll
    for (int r = 0; r < 8; r++) {
        float v = acc[r] * (1.f / 3.f);
        __half hi = __float2half_rn(v);
        __half lo = __float2half_rn(v - __half2float(hi));
        g_avg_hi[base + t + r * 128] = hi;
        g_avg_lo[base + t + r * 128] = lo;
    }
}

// ---------------------------------------------------------------------------
extern "C" void kernel_launch(void* const* d_in, const int* in_sizes, int n_in,
                              void* d_out, int out_size)
{
    (void)in_sizes; (void)n_in; (void)out_size;

    cudaFuncSetAttribute(gemm_mma, cudaFuncAttributeMaxDynamicSharedMemorySize, DYN_SMEM);

    // one fused decompose launch
    {
        const size_t total = 3 * IN2 + 10 * W2;
        const int blocks = (int)((total + 255) / 256);
        decompose_all<<<blocks, 256>>>(
            (const float*)d_in[0], (const float*)d_in[1], (const float*)d_in[2],
            (const float*)d_in[3], (const float*)d_in[5], (const float*)d_in[7],
            (const float*)d_in[9], (const float*)d_in[11], (const float*)d_in[13],
            (const float*)d_in[15], (const float*)d_in[17], (const float*)d_in[19],
            (const float*)d_in[21]);
    }

    // g_w: 0=Wq1 1=Wk1 2=Wv1 3=Wq2 4=Wk2 5=Wv2 6=Wq3 7=Wk3 8=Wv3 9=Wo
    // proj: 0 Q1  1 K1  2 V1  3 Q2  4 K2  5 V2  6 Q3  7 K3  8 V3
    // query: Q1=q@Wq1->p0(b4)   V2=q@Wv2->p5(b14)  K3=q@Wk3->p7(b18)
    // key:   V1=k@Wv1->p2(b8)   K2=k@Wk1->p4(b6)   Q3=k@Wq3->p6(b16)
    // value: K1=v@Wk2->p1(b12)  Q2=v@Wq2->p3(b10)  V3=v@Wv3->p8(b20)
    dim3 gproj(24, 128);
    gemm_mma<<<gproj, 256, DYN_SMEM>>>(0,
        0, 5, 7,
        (const float*)d_in[4], (const float*)d_in[14], (const float*)d_in[18],
        0, 5, 7, nullptr, 0);
    gemm_mma<<<gproj, 256, DYN_SMEM>>>(1,
        2, 1, 6,
        (const float*)d_in[8], (const float*)d_in[6], (const float*)d_in[16],
        2, 4, 6, nullptr, 0);
    gemm_mma<<<gproj, 256, DYN_SMEM>>>(2,
        4, 3, 8,
        (const float*)d_in[12], (const float*)d_in[10], (const float*)d_in[20],
        1, 3, 8, nullptr, 0);

    attn_kernel<<<NTOK, 128>>>();

    // final: out = relu(avg @ Wo^T + bo)
    dim3 gfin(8, 128);
    gemm_mma<<<gfin, 256, DYN_SMEM>>>(3,
        9, 9, 9,
        (const float*)d_in[22], (const float*)d_in[22], (const float*)d_in[22],
        -1, -1, -1, (float*)d_out, 1);
}

// round 7
// speedup vs baseline: 3.9703x; 1.1101x over previous
#include <cuda_runtime.h>
#include <cuda_fp16.h>
#include <cstdint>

#define NTOK 16384
#define DIM  1024
#define NH   16

// ---------------- scratch (allocation-free __device__ globals) ----------------
__device__ float g_proj[9][(size_t)NTOK * DIM];          // fp32 projections
__device__ __half g_in_hi[3][(size_t)NTOK * DIM];        // q,k,v hi (row-major)
__device__ __half g_in_lo[3][(size_t)NTOK * DIM];
__device__ __half g_avg_hi[(size_t)NTOK * DIM];          // averaged attn out
__device__ __half g_avg_lo[(size_t)NTOK * DIM];
__device__ __half g_w_hi[10][(size_t)DIM * DIM];         // weights hi (row-major [N,K])

__device__ __forceinline__ uint32_t smem_u32(const void* p) {
    uint32_t a;
    asm("{ .reg .u64 t; cvta.to.shared.u64 t, %1; cvt.u32.u64 %0, t; }" : "=r"(a) : "l"(p));
    return a;
}

#define MMA16816(C, a0, a1, a2, a3, b0, b1)                                          \
    asm volatile("mma.sync.aligned.m16n8k16.row.col.f32.f16.f16.f32 "                \
        "{%0,%1,%2,%3}, {%4,%5,%6,%7}, {%8,%9}, {%0,%1,%2,%3};"                      \
        : "+f"((C)[0]), "+f"((C)[1]), "+f"((C)[2]), "+f"((C)[3])                     \
        : "r"(a0), "r"(a1), "r"(a2), "r"(a3), "r"(b0), "r"(b1))

// ---------------- fused decompose: all 13 tensors in ONE launch ----------------
#define IN2 ((size_t)NTOK * 512)
#define W2  ((size_t)DIM * 512)

__global__ void decompose_all(
    const float* __restrict__ q, const float* __restrict__ k, const float* __restrict__ v,
    const float* __restrict__ w0, const float* __restrict__ w1, const float* __restrict__ w2,
    const float* __restrict__ w3, const float* __restrict__ w4, const float* __restrict__ w5,
    const float* __restrict__ w6, const float* __restrict__ w7, const float* __restrict__ w8,
    const float* __restrict__ w9)
{
    size_t i = (size_t)blockIdx.x * blockDim.x + threadIdx.x;
    const size_t NIN = 3 * IN2;
    if (i < NIN) {
        int sel = (int)(i / IN2);
        size_t off = (i - (size_t)sel * IN2) * 2;
        const float* src = (sel == 0) ? q : (sel == 1) ? k : v;
        float2 x = *(const float2*)(src + off);
        __half h0 = __float2half_rn(x.x);
        __half h1 = __float2half_rn(x.y);
        __half l0 = __float2half_rn(x.x - __half2float(h0));
        __half l1 = __float2half_rn(x.y - __half2float(h1));
        __half2 hv; hv.x = h0; hv.y = h1;
        __half2 lv; lv.x = l0; lv.y = l1;
        *(__half2*)(g_in_hi[sel] + off) = hv;
        *(__half2*)(g_in_lo[sel] + off) = lv;
    } else {
        size_t j = i - NIN;
        if (j >= 10 * W2) return;
        int sel = (int)(j / W2);
        size_t off = (j - (size_t)sel * W2) * 2;
        const float* ws[10] = {w0, w1, w2, w3, w4, w5, w6, w7, w8, w9};
        float2 x = *(const float2*)(ws[sel] + off);
        __half2 hv;
        hv.x = __float2half_rn(x.x);
        hv.y = __float2half_rn(x.y);
        *(__half2*)(g_w_hi[sel] + off) = hv;
    }
}

// ---------------- fp16 2-pass HMMA GEMM, BK=64, 2-stage (unchanged from R6) ------
#define ROWB 144
#define TILEB (128 * ROWB)
#define STAGEB (3 * TILEB)
#define DYN_SMEM (2 * STAGEB)
#define NC 16

__global__ __launch_bounds__(256, 2)
void gemm_mma(int a_sel,
              int w0, int w1, int w2,
              const float* __restrict__ b0p, const float* __restrict__ b1p, const float* __restrict__ b2p,
              int o0, int o1, int o2, float* __restrict__ dext, int do_relu)
{
    extern __shared__ __align__(16) char dsm[];

    const int tid = threadIdx.x;
    const int wid = tid >> 5;
    const int lane = tid & 31;
    const int kb = blockIdx.x >> 3;
    const int xb = blockIdx.x & 7;
    const int by = blockIdx.y;

    const __half* Ahi = (a_sel < 3) ? g_in_hi[a_sel] : g_avg_hi;
    const __half* Alo = (a_sel < 3) ? g_in_lo[a_sel] : g_avg_lo;
    const int wsel = (kb == 0) ? w0 : (kb == 1) ? w1 : w2;
    const float* bias = (kb == 0) ? b0p : (kb == 1) ? b1p : b2p;
    const int osel = (kb == 0) ? o0 : (kb == 1) ? o1 : o2;
    const __half* Bhi = g_w_hi[wsel];
    float* C = (osel >= 0) ? g_proj[osel] : dext;

    const uint32_t smu = smem_u32(dsm);

    const int lr = tid >> 3;
    const int lseg = (tid & 7) * 8;
    size_t gA[4], gB[4];
    uint32_t sOff[4];
    #pragma unroll
    for (int j = 0; j < 4; j++) {
        int r = lr + j * 32;
        gA[j] = (size_t)(by * 128 + r) * DIM + lseg;
        gB[j] = (size_t)(xb * 128 + r) * DIM + lseg;
        sOff[j] = (uint32_t)(r * ROWB + (tid & 7) * 16);
    }

    const int warp_m = (wid >> 2) * 64;
    const int warp_n = (wid & 3) * 32;
    const int quad = lane >> 3, l7 = lane & 7;
    const uint32_t aoff = (uint32_t)((warp_m + (quad & 1) * 8 + l7) * ROWB + (quad >> 1) * 16);
    const uint32_t boff = (uint32_t)((warp_n + (quad >> 1) * 8 + l7) * ROWB + (quad & 1) * 16);

    float acc[4][4][4];
    #pragma unroll
    for (int i = 0; i < 4; i++)
        #pragma unroll
        for (int j = 0; j < 4; j++)
            #pragma unroll
            for (int r = 0; r < 4; r++) acc[i][j][r] = 0.f;

    auto issue_chunk = [&](int c, int stg) {
        const int ko = c << 6;
        const uint32_t sb = smu + stg * STAGEB;
        #pragma unroll
        for (int j = 0; j < 4; j++) {
            asm volatile("cp.async.cg.shared.global [%0], [%1], 16;"
                         :: "r"(sb + sOff[j]), "l"(Ahi + gA[j] + ko));
            asm volatile("cp.async.cg.shared.global [%0], [%1], 16;"
                         :: "r"(sb + TILEB + sOff[j]), "l"(Alo + gA[j] + ko));
            asm volatile("cp.async.cg.shared.global [%0], [%1], 16;"
                         :: "r"(sb + 2 * TILEB + sOff[j]), "l"(Bhi + gB[j] + ko));
        }
        asm volatile("cp.async.commit_group;");
    };

    issue_chunk(0, 0);

    for (int c = 0; c < NC; c++) {
        asm volatile("cp.async.wait_group 0;");
        __syncthreads();
        if (c + 1 < NC) issue_chunk(c + 1, (c + 1) & 1);

        const uint32_t sb = smu + (c & 1) * STAGEB;
        #pragma unroll
        for (int ks = 0; ks < 4; ks++) {
            uint32_t bf[2][4];
            #pragma unroll
            for (int nt = 0; nt < 2; nt++) {
                uint32_t addr = sb + 2 * TILEB + boff + nt * (16 * ROWB) + ks * 32;
                asm volatile("ldmatrix.sync.aligned.m8n8.x4.shared.b16 {%0,%1,%2,%3}, [%4];"
                             : "=r"(bf[nt][0]), "=r"(bf[nt][1]), "=r"(bf[nt][2]), "=r"(bf[nt][3])
                             : "r"(addr));
            }
            uint32_t af[4][4];
            #pragma unroll
            for (int mt = 0; mt < 4; mt++) {
                uint32_t addr = sb + aoff + mt * (16 * ROWB) + ks * 32;
                asm volatile("ldmatrix.sync.aligned.m8n8.x4.shared.b16 {%0,%1,%2,%3}, [%4];"
                             : "=r"(af[mt][0]), "=r"(af[mt][1]), "=r"(af[mt][2]), "=r"(af[mt][3])
                             : "r"(addr));
            }
            #pragma unroll
            for (int mt = 0; mt < 4; mt++)
                #pragma unroll
                for (int n8 = 0; n8 < 4; n8++)
                    MMA16816(acc[mt][n8],
                             af[mt][0], af[mt][1], af[mt][2], af[mt][3],
                             bf[n8 >> 1][(n8 & 1) * 2 + 0], bf[n8 >> 1][(n8 & 1) * 2 + 1]);
            #pragma unroll
            for (int mt = 0; mt < 4; mt++) {
                uint32_t addr = sb + TILEB + aoff + mt * (16 * ROWB) + ks * 32;
                asm volatile("ldmatrix.sync.aligned.m8n8.x4.shared.b16 {%0,%1,%2,%3}, [%4];"
                             : "=r"(af[mt][0]), "=r"(af[mt][1]), "=r"(af[mt][2]), "=r"(af[mt][3])
                             : "r"(addr));
            }
            #pragma unroll
            for (int mt = 0; mt < 4; mt++)
                #pragma unroll
                for (int n8 = 0; n8 < 4; n8++)
                    MMA16816(acc[mt][n8],
                             af[mt][0], af[mt][1], af[mt][2], af[mt][3],
                             bf[n8 >> 1][(n8 & 1) * 2 + 0], bf[n8 >> 1][(n8 & 1) * 2 + 1]);
        }
    }

    const int erow0 = by * 128 + warp_m + (lane >> 2);
    const int ecol0 = xb * 128 + warp_n + 2 * (lane & 3);
    #pragma unroll
    for (int mt = 0; mt < 4; mt++) {
        #pragma unroll
        for (int n8 = 0; n8 < 4; n8++) {
            const int col = ecol0 + n8 * 8;
            const float bb0 = bias[col], bb1 = bias[col + 1];
            #pragma unroll
            for (int h = 0; h < 2; h++) {
                const int row = erow0 + mt * 16 + h * 8;
                float2 v;
                v.x = acc[mt][n8][2 * h + 0] + bb0;
                v.y = acc[mt][n8][2 * h + 1] + bb1;
                if (do_relu) { v.x = fmaxf(v.x, 0.f); v.y = fmaxf(v.y, 0.f); }
                *(float2*)(C + (size_t)row * DIM + col) = v;
            }
        }
    }
}

// ---------------- tensor-core attention x3 + average ----------------
// Per token: S = Q(64x16)@K^T, softmax over d (cols of S[d][e]), o = W@V(64x16).
// Q,K staged transposed fp16 [d|e][h] stride 24; V,W staged hi/lo fp16 half2
// rows stride 36 (conflict-free fragment loads). o = Wh*Vh + Wh*Vl + Wl*Vh.
__global__ __launch_bounds__(128)
void attn_kernel()
{
    __shared__ float Sf[64 * 65];            // scores [e][d], reused as o[h*64+d] at end
    __shared__ __half Qt[64 * 24];           // [d][h]
    __shared__ __half Kt[64 * 24];           // [e][h]
    __shared__ uint32_t Vh[16 * 36], Vl[16 * 36];   // half2 rows [h][e2]
    __shared__ uint32_t Wh[64 * 36], Wl[64 * 36];   // half2 rows [d][e2]
    __shared__ float red[128];

    const int n = blockIdx.x;
    const int t = threadIdx.x;
    const int w = t >> 5;
    const int l = t & 31;
    const int r = l >> 2;       // fragment row group
    const int cq = l & 3;       // fragment col group

    float oacc[2][4];
    #pragma unroll
    for (int nt = 0; nt < 2; nt++)
        #pragma unroll
        for (int j = 0; j < 4; j++) oacc[nt][j] = 0.f;

    for (int a = 0; a < 3; a++) {
        const float4* Qp = (const float4*)(g_proj[3 * a + 0] + (size_t)n * DIM);
        const float4* Kp = (const float4*)(g_proj[3 * a + 1] + (size_t)n * DIM);
        const float4* Vp = (const float4*)(g_proj[3 * a + 2] + (size_t)n * DIM);

        // stage + convert: thread t covers elements i = t*8 .. t*8+7 (single h row)
        {
            const int h = t >> 3;            // i>>6
            const int d0 = (t & 7) * 8;      // i&63
            float4 x0 = Qp[t * 2], x1 = Qp[t * 2 + 1];
            float xs[8] = {x0.x, x0.y, x0.z, x0.w, x1.x, x1.y, x1.z, x1.w};
            #pragma unroll
            for (int j = 0; j < 8; j++) Qt[(d0 + j) * 24 + h] = __float2half_rn(xs[j]);

            float4 k0 = Kp[t * 2], k1 = Kp[t * 2 + 1];
            float ks_[8] = {k0.x, k0.y, k0.z, k0.w, k1.x, k1.y, k1.z, k1.w};
            #pragma unroll
            for (int j = 0; j < 8; j++) Kt[(d0 + j) * 24 + h] = __float2half_rn(ks_[j]);

            float4 v0 = Vp[t * 2], v1 = Vp[t * 2 + 1];
            float vs[8] = {v0.x, v0.y, v0.z, v0.w, v1.x, v1.y, v1.z, v1.w};
            #pragma unroll
            for (int j = 0; j < 4; j++) {
                __half h0 = __float2half_rn(vs[2 * j]);
                __half h1 = __float2half_rn(vs[2 * j + 1]);
                __half2 hv; hv.x = h0; hv.y = h1;
                __half2 lv;
                lv.x = __float2half_rn(vs[2 * j] - __half2float(h0));
                lv.y = __float2half_rn(vs[2 * j + 1] - __half2float(h1));
                Vh[h * 36 + d0 / 2 + j] = *(uint32_t*)&hv;
                Vl[h * 36 + d0 / 2 + j] = *(uint32_t*)&lv;
            }
        }
        __syncthreads();

        // scores mma: warp w -> rows d in [16w, 16w+16)
        {
            uint32_t a0 = *(uint32_t*)&Qt[(16 * w + r) * 24 + 2 * cq];
            uint32_t a1 = *(uint32_t*)&Qt[(16 * w + r + 8) * 24 + 2 * cq];
            uint32_t a2 = *(uint32_t*)&Qt[(16 * w + r) * 24 + 2 * cq + 8];
            uint32_t a3 = *(uint32_t*)&Qt[(16 * w + r + 8) * 24 + 2 * cq + 8];
            #pragma unroll
            for (int nt = 0; nt < 8; nt++) {
                const int e0 = nt * 8;
                uint32_t b0 = *(uint32_t*)&Kt[(e0 + r) * 24 + 2 * cq];
                uint32_t b1 = *(uint32_t*)&Kt[(e0 + r) * 24 + 2 * cq + 8];
                float c[4] = {0.f, 0.f, 0.f, 0.f};
                MMA16816(c, a0, a1, a2, a3, b0, b1);
                const int d = 16 * w + r;
                const int e = e0 + 2 * cq;
                Sf[e * 65 + d]            = c[0] * 0.125f;
                Sf[(e + 1) * 65 + d]      = c[1] * 0.125f;
                Sf[e * 65 + d + 8]        = c[2] * 0.125f;
                Sf[(e + 1) * 65 + d + 8]  = c[3] * 0.125f;
            }
        }
        __syncthreads();

        // softmax over d per column e (parallel halves)
        {
            const int e = t & 63;
            const int d0 = (t >> 6) * 32;
            float m = -1e30f;
            #pragma unroll 8
            for (int d = 0; d < 32; d++) m = fmaxf(m, Sf[e * 65 + d0 + d]);
            red[t] = m;
            __syncthreads();
            m = fmaxf(red[e], red[e + 64]);
            __syncthreads();
            float sum = 0.f;
            #pragma unroll 8
            for (int d = 0; d < 32; d++) {
                float ex = __expf(Sf[e * 65 + d0 + d] - m);
                Sf[e * 65 + d0 + d] = ex;
                sum += ex;
            }
            red[t] = sum;
            __syncthreads();
            const float inv = 1.f / (red[e] + red[e + 64]);
            #pragma unroll 8
            for (int d = 0; d < 32; d++) Sf[e * 65 + d0 + d] *= inv;
        }
        __syncthreads();

        // convert W -> fp16 hi/lo, layout [d][e] half2 rows stride 36
        for (int idx = t; idx < 2048; idx += 128) {
            const int d = idx >> 5;
            const int e2 = idx & 31;
            float w0 = Sf[(2 * e2) * 65 + d];
            float w1 = Sf[(2 * e2 + 1) * 65 + d];
            __half h0 = __float2half_rn(w0);
            __half h1 = __float2half_rn(w1);
            __half2 hv; hv.x = h0; hv.y = h1;
            __half2 lv;
            lv.x = __float2half_rn(w0 - __half2float(h0));
            lv.y = __float2half_rn(w1 - __half2float(h1));
            Wh[d * 36 + e2] = *(uint32_t*)&hv;
            Wl[d * 36 + e2] = *(uint32_t*)&lv;
        }
        __syncthreads();

        // o mma: o(64x16) = Wh@Vh + Wh@Vl + Wl@Vh; warp w rows d in [16w,16w+16)
        {
            #pragma unroll
            for (int ks = 0; ks < 4; ks++) {
                uint32_t ah0 = Wh[(16 * w + r) * 36 + 8 * ks + cq];
                uint32_t ah1 = Wh[(16 * w + r + 8) * 36 + 8 * ks + cq];
                uint32_t ah2 = Wh[(16 * w + r) * 36 + 8 * ks + cq + 4];
                uint32_t ah3 = Wh[(16 * w + r + 8) * 36 + 8 * ks + cq + 4];
                uint32_t al0 = Wl[(16 * w + r) * 36 + 8 * ks + cq];
                uint32_t al1 = Wl[(16 * w + r + 8) * 36 + 8 * ks + cq];
                uint32_t al2 = Wl[(16 * w + r) * 36 + 8 * ks + cq + 4];
                uint32_t al3 = Wl[(16 * w + r + 8) * 36 + 8 * ks + cq + 4];
                #pragma unroll
                for (int nt = 0; nt < 2; nt++) {
                    const int h0 = nt * 8;
                    uint32_t vh0 = Vh[(h0 + r) * 36 + 8 * ks + cq];
                    uint32_t vh1 = Vh[(h0 + r) * 36 + 8 * ks + cq + 4];
                    uint32_t vl0 = Vl[(h0 + r) * 36 + 8 * ks + cq];
                    uint32_t vl1 = Vl[(h0 + r) * 36 + 8 * ks + cq + 4];
                    MMA16816(oacc[nt], ah0, ah1, ah2, ah3, vh0, vh1);
                    MMA16816(oacc[nt], ah0, ah1, ah2, ah3, vl0, vl1);
                    MMA16816(oacc[nt], al0, al1, al2, al3, vh0, vh1);
                }
            }
        }
        __syncthreads();
    }

    // write o fragments to smem (reuse Sf as o[h*64+d]), then coalesced gmem write
    float* os = Sf;
    {
        #pragma unroll
        for (int nt = 0; nt < 2; nt++) {
            const int h = nt * 8 + 2 * cq;
            const int d = 16 * w + r;
            os[h * 64 + d]           = oacc[nt][0];
            os[(h + 1) * 64 + d]     = oacc[nt][1];
            os[h * 64 + d + 8]       = oacc[nt][2];
            os[(h + 1) * 64 + d + 8] = oacc[nt][3];
        }
    }
    __syncthreads();

    const size_t base = (size_t)n * DIM;
    #pragma unroll
    for (int rr = 0; rr < 8; rr++) {
        const int i = t + rr * 128;
        float v = os[i] * (1.f / 3.f);
        __half hi = __float2half_rn(v);
        __half lo = __float2half_rn(v - __half2float(hi));
        g_avg_hi[base + i] = hi;
        g_avg_lo[base + i] = lo;
    }
}

// ---------------------------------------------------------------------------
extern "C" void kernel_launch(void* const* d_in, const int* in_sizes, int n_in,
                              void* d_out, int out_size)
{
    (void)in_sizes; (void)n_in; (void)out_size;

    cudaFuncSetAttribute(gemm_mma, cudaFuncAttributeMaxDynamicSharedMemorySize, DYN_SMEM);

    {
        const size_t total = 3 * IN2 + 10 * W2;
        const int blocks = (int)((total + 255) / 256);
        decompose_all<<<blocks, 256>>>(
            (const float*)d_in[0], (const float*)d_in[1], (const float*)d_in[2],
            (const float*)d_in[3], (const float*)d_in[5], (const float*)d_in[7],
            (const float*)d_in[9], (const float*)d_in[11], (const float*)d_in[13],
            (const float*)d_in[15], (const float*)d_in[17], (const float*)d_in[19],
            (const float*)d_in[21]);
    }

    // g_w: 0=Wq1 1=Wk1 2=Wv1 3=Wq2 4=Wk2 5=Wv2 6=Wq3 7=Wk3 8=Wv3 9=Wo
    // proj: 0 Q1  1 K1  2 V1  3 Q2  4 K2  5 V2  6 Q3  7 K3  8 V3
    dim3 gproj(24, 128);
    gemm_mma<<<gproj, 256, DYN_SMEM>>>(0,
        0, 5, 7,
        (const float*)d_in[4], (const float*)d_in[14], (const float*)d_in[18],
        0, 5, 7, nullptr, 0);
    gemm_mma<<<gproj, 256, DYN_SMEM>>>(1,
        2, 1, 6,
        (const float*)d_in[8], (const float*)d_in[6], (const float*)d_in[16],
        2, 4, 6, nullptr, 0);
    gemm_mma<<<gproj, 256, DYN_SMEM>>>(2,
        4, 3, 8,
        (const float*)d_in[12], (const float*)d_in[10], (const float*)d_in[20],
        1, 3, 8, nullptr, 0);

    attn_kernel<<<NTOK, 128>>>();

    dim3 gfin(8, 128);
    gemm_mma<<<gfin, 256, DYN_SMEM>>>(3,
        9, 9, 9,
        (const float*)d_in[22], (const float*)d_in[22], (const float*)d_in[22],
        -1, -1, -1, (float*)d_out, 1);
}

// round 8
// speedup vs baseline: 5.7142x; 1.4392x over previous
#include <cuda_runtime.h>
#include <cuda_fp16.h>
#include <cstdint>

#define NTOK 16384
#define DIM  1024
#define NH   16

// ---------------- scratch (allocation-free __device__ globals) ----------------
__device__ float g_proj[9][(size_t)NTOK * DIM];          // fp32 projections
__device__ __half g_in_hi[3][(size_t)NTOK * DIM];        // q,k,v fp16 (row-major)
__device__ __half g_avg_hi[(size_t)NTOK * DIM];          // averaged attn out fp16
__device__ __half g_w_hi[10][(size_t)DIM * DIM];         // weights fp16 (row-major [N,K])

__device__ __forceinline__ uint32_t smem_u32(const void* p) {
    uint32_t a;
    asm("{ .reg .u64 t; cvta.to.shared.u64 t, %1; cvt.u32.u64 %0, t; }" : "=r"(a) : "l"(p));
    return a;
}

#define MMA16816(C, a0, a1, a2, a3, b0, b1)                                          \
    asm volatile("mma.sync.aligned.m16n8k16.row.col.f32.f16.f16.f32 "                \
        "{%0,%1,%2,%3}, {%4,%5,%6,%7}, {%8,%9}, {%0,%1,%2,%3};"                      \
        : "+f"((C)[0]), "+f"((C)[1]), "+f"((C)[2]), "+f"((C)[3])                     \
        : "r"(a0), "r"(a1), "r"(a2), "r"(a3), "r"(b0), "r"(b1))

// ---------------- fused fp32 -> fp16 convert: all 13 tensors, ONE launch ----------
#define IN2 ((size_t)NTOK * 512)
#define W2  ((size_t)DIM * 512)

__global__ void decompose_all(
    const float* __restrict__ q, const float* __restrict__ k, const float* __restrict__ v,
    const float* __restrict__ w0, const float* __restrict__ w1, const float* __restrict__ w2,
    const float* __restrict__ w3, const float* __restrict__ w4, const float* __restrict__ w5,
    const float* __restrict__ w6, const float* __restrict__ w7, const float* __restrict__ w8,
    const float* __restrict__ w9)
{
    size_t i = (size_t)blockIdx.x * blockDim.x + threadIdx.x;
    const size_t NIN = 3 * IN2;
    const float* src;
    __half* dst;
    size_t off;
    if (i < NIN) {
        int sel = (int)(i / IN2);
        off = (i - (size_t)sel * IN2) * 2;
        src = (sel == 0) ? q : (sel == 1) ? k : v;
        dst = g_in_hi[sel];
    } else {
        size_t j = i - NIN;
        if (j >= 10 * W2) return;
        int sel = (int)(j / W2);
        off = (j - (size_t)sel * W2) * 2;
        const float* ws[10] = {w0, w1, w2, w3, w4, w5, w6, w7, w8, w9};
        src = ws[sel];
        dst = g_w_hi[sel];
    }
    float2 x = *(const float2*)(src + off);
    __half2 hv;
    hv.x = __float2half_rn(x.x);
    hv.y = __float2half_rn(x.y);
    *(__half2*)(dst + off) = hv;
}

// ---------------- fp16 single-pass HMMA GEMM, BK=64, 3-stage ----------------
// C = A @ W^T + bias (opt ReLU). Up to 3 kilo-blocks in N.
// a_sel: 0..2 = g_in[q/k/v], 3 = g_avg.  osel >= 0 -> g_proj[osel], else dext.
#define ROWB 144                    // 128B data + 16B pad
#define TILEB (128 * ROWB)          // 18432 B
#define STAGEB (2 * TILEB)          // A, B
#define NSTAGE 3
#define DYN_SMEM (NSTAGE * STAGEB)  // 110592 B
#define NC 16

__global__ __launch_bounds__(256, 2)
void gemm_mma(int a_sel,
              int w0, int w1, int w2,
              const float* __restrict__ b0p, const float* __restrict__ b1p, const float* __restrict__ b2p,
              int o0, int o1, int o2, float* __restrict__ dext, int do_relu)
{
    extern __shared__ __align__(16) char dsm[];

    const int tid = threadIdx.x;
    const int wid = tid >> 5;
    const int lane = tid & 31;
    const int kb = blockIdx.x >> 3;
    const int xb = blockIdx.x & 7;
    const int by = blockIdx.y;

    const __half* Ahi = (a_sel < 3) ? g_in_hi[a_sel] : g_avg_hi;
    const int wsel = (kb == 0) ? w0 : (kb == 1) ? w1 : w2;
    const float* bias = (kb == 0) ? b0p : (kb == 1) ? b1p : b2p;
    const int osel = (kb == 0) ? o0 : (kb == 1) ? o1 : o2;
    const __half* Bhi = g_w_hi[wsel];
    float* C = (osel >= 0) ? g_proj[osel] : dext;

    const uint32_t smu = smem_u32(dsm);

    // loader: per tile 4 segs/thread; rows (tid>>3)+{0,32,64,96}, 16B seg tid&7
    const int lr = tid >> 3;
    const int lseg = (tid & 7) * 8;
    size_t gA[4], gB[4];
    uint32_t sOff[4];
    #pragma unroll
    for (int j = 0; j < 4; j++) {
        int r = lr + j * 32;
        gA[j] = (size_t)(by * 128 + r) * DIM + lseg;
        gB[j] = (size_t)(xb * 128 + r) * DIM + lseg;
        sOff[j] = (uint32_t)(r * ROWB + (tid & 7) * 16);
    }

    // warp tiling: 8 warps 2x4, warp tile 64x32
    const int warp_m = (wid >> 2) * 64;
    const int warp_n = (wid & 3) * 32;
    const int quad = lane >> 3, l7 = lane & 7;
    const uint32_t aoff = (uint32_t)((warp_m + (quad & 1) * 8 + l7) * ROWB + (quad >> 1) * 16);
    const uint32_t boff = (uint32_t)((warp_n + (quad >> 1) * 8 + l7) * ROWB + (quad & 1) * 16);

    float acc[4][4][4];
    #pragma unroll
    for (int i = 0; i < 4; i++)
        #pragma unroll
        for (int j = 0; j < 4; j++)
            #pragma unroll
            for (int r = 0; r < 4; r++) acc[i][j][r] = 0.f;

    auto issue_chunk = [&](int c, int stg) {
        const int ko = c << 6;                        // 64 elements per chunk
        const uint32_t sb = smu + stg * STAGEB;
        #pragma unroll
        for (int j = 0; j < 4; j++) {
            asm volatile("cp.async.cg.shared.global [%0], [%1], 16;"
                         :: "r"(sb + sOff[j]), "l"(Ahi + gA[j] + ko));
            asm volatile("cp.async.cg.shared.global [%0], [%1], 16;"
                         :: "r"(sb + TILEB + sOff[j]), "l"(Bhi + gB[j] + ko));
        }
        asm volatile("cp.async.commit_group;");
    };

    issue_chunk(0, 0);
    issue_chunk(1, 1);

    int stg = 0;
    for (int c = 0; c < NC; c++) {
        if (c + 1 < NC) asm volatile("cp.async.wait_group 1;");
        else            asm volatile("cp.async.wait_group 0;");
        __syncthreads();

        if (c + 2 < NC) {
            int nstg = stg + 2; if (nstg >= NSTAGE) nstg -= NSTAGE;
            issue_chunk(c + 2, nstg);
        }

        const uint32_t sb = smu + stg * STAGEB;
        #pragma unroll
        for (int ks = 0; ks < 4; ks++) {
            uint32_t bf[2][4];
            #pragma unroll
            for (int nt = 0; nt < 2; nt++) {
                uint32_t addr = sb + TILEB + boff + nt * (16 * ROWB) + ks * 32;
                asm volatile("ldmatrix.sync.aligned.m8n8.x4.shared.b16 {%0,%1,%2,%3}, [%4];"
                             : "=r"(bf[nt][0]), "=r"(bf[nt][1]), "=r"(bf[nt][2]), "=r"(bf[nt][3])
                             : "r"(addr));
            }
            uint32_t af[4][4];
            #pragma unroll
            for (int mt = 0; mt < 4; mt++) {
                uint32_t addr = sb + aoff + mt * (16 * ROWB) + ks * 32;
                asm volatile("ldmatrix.sync.aligned.m8n8.x4.shared.b16 {%0,%1,%2,%3}, [%4];"
                             : "=r"(af[mt][0]), "=r"(af[mt][1]), "=r"(af[mt][2]), "=r"(af[mt][3])
                             : "r"(addr));
            }
            #pragma unroll
            for (int mt = 0; mt < 4; mt++)
                #pragma unroll
                for (int n8 = 0; n8 < 4; n8++)
                    MMA16816(acc[mt][n8],
                             af[mt][0], af[mt][1], af[mt][2], af[mt][3],
                             bf[n8 >> 1][(n8 & 1) * 2 + 0], bf[n8 >> 1][(n8 & 1) * 2 + 1]);
        }
        stg++; if (stg >= NSTAGE) stg = 0;
    }

    // epilogue
    const int erow0 = by * 128 + warp_m + (lane >> 2);
    const int ecol0 = xb * 128 + warp_n + 2 * (lane & 3);
    #pragma unroll
    for (int mt = 0; mt < 4; mt++) {
        #pragma unroll
        for (int n8 = 0; n8 < 4; n8++) {
            const int col = ecol0 + n8 * 8;
            const float bb0 = bias[col], bb1 = bias[col + 1];
            #pragma unroll
            for (int h = 0; h < 2; h++) {
                const int row = erow0 + mt * 16 + h * 8;
                float2 v;
                v.x = acc[mt][n8][2 * h + 0] + bb0;
                v.y = acc[mt][n8][2 * h + 1] + bb1;
                if (do_relu) { v.x = fmaxf(v.x, 0.f); v.y = fmaxf(v.y, 0.f); }
                *(float2*)(C + (size_t)row * DIM + col) = v;
            }
        }
    }
}

// ---------------- tensor-core attention x3 + average ----------------
// Per token: S = Q(64x16)@K^T, softmax over d, o = W@V via hi/lo 3-pass.
__global__ __launch_bounds__(128)
void attn_kernel()
{
    __shared__ float Sf[64 * 65];            // scores [e][d]; reused as o[h*64+d]
    __shared__ __half Qt[64 * 24];           // [d][h]
    __shared__ __half Kt[64 * 24];           // [e][h]
    __shared__ uint32_t Vh[16 * 36], Vl[16 * 36];   // half2 rows [h][e2]
    __shared__ uint32_t Wh[64 * 36], Wl[64 * 36];   // half2 rows [d][e2]
    __shared__ float red[128];

    const int n = blockIdx.x;
    const int t = threadIdx.x;
    const int w = t >> 5;
    const int l = t & 31;
    const int r = l >> 2;
    const int cq = l & 3;

    float oacc[2][4];
    #pragma unroll
    for (int nt = 0; nt < 2; nt++)
        #pragma unroll
        for (int j = 0; j < 4; j++) oacc[nt][j] = 0.f;

    for (int a = 0; a < 3; a++) {
        const float4* Qp = (const float4*)(g_proj[3 * a + 0] + (size_t)n * DIM);
        const float4* Kp = (const float4*)(g_proj[3 * a + 1] + (size_t)n * DIM);
        const float4* Vp = (const float4*)(g_proj[3 * a + 2] + (size_t)n * DIM);

        {
            const int h = t >> 3;
            const int d0 = (t & 7) * 8;
            float4 x0 = Qp[t * 2], x1 = Qp[t * 2 + 1];
            float xs[8] = {x0.x, x0.y, x0.z, x0.w, x1.x, x1.y, x1.z, x1.w};
            #pragma unroll
            for (int j = 0; j < 8; j++) Qt[(d0 + j) * 24 + h] = __float2half_rn(xs[j]);

            float4 k0 = Kp[t * 2], k1 = Kp[t * 2 + 1];
            float ks_[8] = {k0.x, k0.y, k0.z, k0.w, k1.x, k1.y, k1.z, k1.w};
            #pragma unroll
            for (int j = 0; j < 8; j++) Kt[(d0 + j) * 24 + h] = __float2half_rn(ks_[j]);

            float4 v0 = Vp[t * 2], v1 = Vp[t * 2 + 1];
            float vs[8] = {v0.x, v0.y, v0.z, v0.w, v1.x, v1.y, v1.z, v1.w};
            #pragma unroll
            for (int j = 0; j < 4; j++) {
                __half h0 = __float2half_rn(vs[2 * j]);
                __half h1 = __float2half_rn(vs[2 * j + 1]);
                __half2 hv; hv.x = h0; hv.y = h1;
                __half2 lv;
                lv.x = __float2half_rn(vs[2 * j] - __half2float(h0));
                lv.y = __float2half_rn(vs[2 * j + 1] - __half2float(h1));
                Vh[h * 36 + d0 / 2 + j] = *(uint32_t*)&hv;
                Vl[h * 36 + d0 / 2 + j] = *(uint32_t*)&lv;
            }
        }
        __syncthreads();

        {
            uint32_t a0 = *(uint32_t*)&Qt[(16 * w + r) * 24 + 2 * cq];
            uint32_t a1 = *(uint32_t*)&Qt[(16 * w + r + 8) * 24 + 2 * cq];
            uint32_t a2 = *(uint32_t*)&Qt[(16 * w + r) * 24 + 2 * cq + 8];
            uint32_t a3 = *(uint32_t*)&Qt[(16 * w + r + 8) * 24 + 2 * cq + 8];
            #pragma unroll
            for (int nt = 0; nt < 8; nt++) {
                const int e0 = nt * 8;
                uint32_t b0 = *(uint32_t*)&Kt[(e0 + r) * 24 + 2 * cq];
                uint32_t b1 = *(uint32_t*)&Kt[(e0 + r) * 24 + 2 * cq + 8];
                float c[4] = {0.f, 0.f, 0.f, 0.f};
                MMA16816(c, a0, a1, a2, a3, b0, b1);
                const int d = 16 * w + r;
                const int e = e0 + 2 * cq;
                Sf[e * 65 + d]            = c[0] * 0.125f;
                Sf[(e + 1) * 65 + d]      = c[1] * 0.125f;
                Sf[e * 65 + d + 8]        = c[2] * 0.125f;
                Sf[(e + 1) * 65 + d + 8]  = c[3] * 0.125f;
            }
        }
        __syncthreads();

        {
            const int e = t & 63;
            const int d0 = (t >> 6) * 32;
            float m = -1e30f;
            #pragma unroll 8
            for (int d = 0; d < 32; d++) m = fmaxf(m, Sf[e * 65 + d0 + d]);
            red[t] = m;
            __syncthreads();
            m = fmaxf(red[e], red[e + 64]);
            __syncthreads();
            float sum = 0.f;
            #pragma unroll 8
            for (int d = 0; d < 32; d++) {
                float ex = __expf(Sf[e * 65 + d0 + d] - m);
                Sf[e * 65 + d0 + d] = ex;
                sum += ex;
            }
            red[t] = sum;
            __syncthreads();
            const float inv = 1.f / (red[e] + red[e + 64]);
            #pragma unroll 8
            for (int d = 0; d < 32; d++) Sf[e * 65 + d0 + d] *= inv;
        }
        __syncthreads();

        for (int idx = t; idx < 2048; idx += 128) {
            const int d = idx >> 5;
            const int e2 = idx & 31;
            float w0 = Sf[(2 * e2) * 65 + d];
            float w1 = Sf[(2 * e2 + 1) * 65 + d];
            __half h0 = __float2half_rn(w0);
            __half h1 = __float2half_rn(w1);
            __half2 hv; hv.x = h0; hv.y = h1;
            __half2 lv;
            lv.x = __float2half_rn(w0 - __half2float(h0));
            lv.y = __float2half_rn(w1 - __half2float(h1));
            Wh[d * 36 + e2] = *(uint32_t*)&hv;
            Wl[d * 36 + e2] = *(uint32_t*)&lv;
        }
        __syncthreads();

        {
            #pragma unroll
            for (int ks = 0; ks < 4; ks++) {
                uint32_t ah0 = Wh[(16 * w + r) * 36 + 8 * ks + cq];
                uint32_t ah1 = Wh[(16 * w + r + 8) * 36 + 8 * ks + cq];
                uint32_t ah2 = Wh[(16 * w + r) * 36 + 8 * ks + cq + 4];
                uint32_t ah3 = Wh[(16 * w + r + 8) * 36 + 8 * ks + cq + 4];
                uint32_t al0 = Wl[(16 * w + r) * 36 + 8 * ks + cq];
                uint32_t al1 = Wl[(16 * w + r + 8) * 36 + 8 * ks + cq];
                uint32_t al2 = Wl[(16 * w + r) * 36 + 8 * ks + cq + 4];
                uint32_t al3 = Wl[(16 * w + r + 8) * 36 + 8 * ks + cq + 4];
                #pragma unroll
                for (int nt = 0; nt < 2; nt++) {
                    const int h0 = nt * 8;
                    uint32_t vh0 = Vh[(h0 + r) * 36 + 8 * ks + cq];
                    uint32_t vh1 = Vh[(h0 + r) * 36 + 8 * ks + cq + 4];
                    uint32_t vl0 = Vl[(h0 + r) * 36 + 8 * ks + cq];
                    uint32_t vl1 = Vl[(h0 + r) * 36 + 8 * ks + cq + 4];
                    MMA16816(oacc[nt], ah0, ah1, ah2, ah3, vh0, vh1);
                    MMA16816(oacc[nt], ah0, ah1, ah2, ah3, vl0, vl1);
                    MMA16816(oacc[nt], al0, al1, al2, al3, vh0, vh1);
                }
            }
        }
        __syncthreads();
    }

    float* os = Sf;
    {
        #pragma unroll
        for (int nt = 0; nt < 2; nt++) {
            const int h = nt * 8 + 2 * cq;
            const int d = 16 * w + r;
            os[h * 64 + d]           = oacc[nt][0];
            os[(h + 1) * 64 + d]     = oacc[nt][1];
            os[h * 64 + d + 8]       = oacc[nt][2];
            os[(h + 1) * 64 + d + 8] = oacc[nt][3];
        }
    }
    __syncthreads();

    const size_t base = (size_t)n * DIM;
    #pragma unroll
    for (int rr = 0; rr < 8; rr++) {
        const int i = t + rr * 128;
        g_avg_hi[base + i] = __float2half_rn(os[i] * (1.f / 3.f));
    }
}

// ---------------------------------------------------------------------------
extern "C" void kernel_launch(void* const* d_in, const int* in_sizes, int n_in,
                              void* d_out, int out_size)
{
    (void)in_sizes; (void)n_in; (void)out_size;

    cudaFuncSetAttribute(gemm_mma, cudaFuncAttributeMaxDynamicSharedMemorySize, DYN_SMEM);

    {
        const size_t total = 3 * IN2 + 10 * W2;
        const int blocks = (int)((total + 255) / 256);
        decompose_all<<<blocks, 256>>>(
            (const float*)d_in[0], (const float*)d_in[1], (const float*)d_in[2],
            (const float*)d_in[3], (const float*)d_in[5], (const float*)d_in[7],
            (const float*)d_in[9], (const float*)d_in[11], (const float*)d_in[13],
            (const float*)d_in[15], (const float*)d_in[17], (const float*)d_in[19],
            (const float*)d_in[21]);
    }

    // g_w: 0=Wq1 1=Wk1 2=Wv1 3=Wq2 4=Wk2 5=Wv2 6=Wq3 7=Wk3 8=Wv3 9=Wo
    // proj: 0 Q1  1 K1  2 V1  3 Q2  4 K2  5 V2  6 Q3  7 K3  8 V3
    dim3 gproj(24, 128);
    gemm_mma<<<gproj, 256, DYN_SMEM>>>(0,
        0, 5, 7,
        (const float*)d_in[4], (const float*)d_in[14], (const float*)d_in[18],
        0, 5, 7, nullptr, 0);
    gemm_mma<<<gproj, 256, DYN_SMEM>>>(1,
        2, 1, 6,
        (const float*)d_in[8], (const float*)d_in[6], (const float*)d_in[16],
        2, 4, 6, nullptr, 0);
    gemm_mma<<<gproj, 256, DYN_SMEM>>>(2,
        4, 3, 8,
        (const float*)d_in[12], (const float*)d_in[10], (const float*)d_in[20],
        1, 3, 8, nullptr, 0);

    attn_kernel<<<NTOK, 128>>>();

    dim3 gfin(8, 128);
    gemm_mma<<<gfin, 256, DYN_SMEM>>>(3,
        9, 9, 9,
        (const float*)d_in[22], (const float*)d_in[22], (const float*)d_in[22],
        -1, -1, -1, (float*)d_out, 1);
}

// round 10
// speedup vs baseline: 6.0543x; 1.0595x over previous
#include <cuda_runtime.h>
#include <cuda_fp16.h>
#include <cstdint>

#define NTOK 16384
#define DIM  1024
#define NH   16

// ---------------- scratch (allocation-free __device__ globals) ----------------
__device__ float g_proj[9][(size_t)NTOK * DIM];          // fp32 projections
__device__ __half g_in_hi[3][(size_t)NTOK * DIM];        // q,k,v fp16 (row-major)
__device__ __half g_avg_hi[(size_t)NTOK * DIM];          // averaged attn out fp16
__device__ __half g_w_hi[10][(size_t)DIM * DIM];         // weights fp16 (row-major [N,K])

__device__ __forceinline__ uint32_t smem_u32(const void* p) {
    uint32_t a;
    asm("{ .reg .u64 t; cvta.to.shared.u64 t, %1; cvt.u32.u64 %0, t; }" : "=r"(a) : "l"(p));
    return a;
}

#define MMA16816(C, a0, a1, a2, a3, b0, b1)                                          \
    asm volatile("mma.sync.aligned.m16n8k16.row.col.f32.f16.f16.f32 "                \
        "{%0,%1,%2,%3}, {%4,%5,%6,%7}, {%8,%9}, {%0,%1,%2,%3};"                      \
        : "+f"((C)[0]), "+f"((C)[1]), "+f"((C)[2]), "+f"((C)[3])                     \
        : "r"(a0), "r"(a1), "r"(a2), "r"(a3), "r"(b0), "r"(b1))

// FMA-pipe exp: 2^n split via magic number + degree-6 Taylor/Horner on r.
// Valid |x| < ~80; rel err ~1.4e-7. No MUFU.
__device__ __forceinline__ float fast_exp(float x) {
    float t = fmaf(x, 1.4426950408889634f, 12582912.0f);   // x*log2e + 1.5*2^23
    float n = t - 12582912.0f;
    int ni = __float_as_int(t);                            // 0x4B400000 + (int)n
    float r = fmaf(n, -0.6931471805599453f, x);            // r in [-0.347, 0.347]
    float p = 1.3888889e-3f;
    p = fmaf(p, r, 8.3333333e-3f);
    p = fmaf(p, r, 4.1666667e-2f);
    p = fmaf(p, r, 1.6666667e-1f);
    p = fmaf(p, r, 0.5f);
    p = fmaf(p, r, 1.0f);
    p = fmaf(p, r, 1.0f);
    int sc = (ni - 0x4B400000 + 127) << 23;                // 2^n
    return p * __int_as_float(sc);
}

// ---------------- fused fp32 -> fp16 convert: all 13 tensors, ONE launch ----------
#define IN2 ((size_t)NTOK * 512)
#define W2  ((size_t)DIM * 512)

__global__ void decompose_all(
    const float* __restrict__ q, const float* __restrict__ k, const float* __restrict__ v,
    const float* __restrict__ w0, const float* __restrict__ w1, const float* __restrict__ w2,
    const float* __restrict__ w3, const float* __restrict__ w4, const float* __restrict__ w5,
    const float* __restrict__ w6, const float* __restrict__ w7, const float* __restrict__ w8,
    const float* __restrict__ w9)
{
    size_t i = (size_t)blockIdx.x * blockDim.x + threadIdx.x;
    const size_t NIN = 3 * IN2;
    const float* src;
    __half* dst;
    size_t off;
    if (i < NIN) {
        int sel = (int)(i / IN2);
        off = (i - (size_t)sel * IN2) * 2;
        src = (sel == 0) ? q : (sel == 1) ? k : v;
        dst = g_in_hi[sel];
    } else {
        size_t j = i - NIN;
        if (j >= 10 * W2) return;
        int sel = (int)(j / W2);
        off = (j - (size_t)sel * W2) * 2;
        const float* ws[10] = {w0, w1, w2, w3, w4, w5, w6, w7, w8, w9};
        src = ws[sel];
        dst = g_w_hi[sel];
    }
    float2 x = *(const float2*)(src + off);
    __half2 hv;
    hv.x = __float2half_rn(x.x);
    hv.y = __float2half_rn(x.y);
    *(__half2*)(dst + off) = hv;
}

// ---------------- fp16 single-pass HMMA GEMM, BK=64, 3-stage (unchanged R8) ------
#define ROWB 144
#define TILEB (128 * ROWB)
#define STAGEB (2 * TILEB)
#define NSTAGE 3
#define DYN_SMEM (NSTAGE * STAGEB)
#define NC 16

__global__ __launch_bounds__(256, 2)
void gemm_mma(int a_sel,
              int w0, int w1, int w2,
              const float* __restrict__ b0p, const float* __restrict__ b1p, const float* __restrict__ b2p,
              int o0, int o1, int o2, float* __restrict__ dext, int do_relu)
{
    extern __shared__ __align__(16) char dsm[];

    const int tid = threadIdx.x;
    const int wid = tid >> 5;
    const int lane = tid & 31;
    const int kb = blockIdx.x >> 3;
    const int xb = blockIdx.x & 7;
    const int by = blockIdx.y;

    const __half* Ahi = (a_sel < 3) ? g_in_hi[a_sel] : g_avg_hi;
    const int wsel = (kb == 0) ? w0 : (kb == 1) ? w1 : w2;
    const float* bias = (kb == 0) ? b0p : (kb == 1) ? b1p : b2p;
    const int osel = (kb == 0) ? o0 : (kb == 1) ? o1 : o2;
    const __half* Bhi = g_w_hi[wsel];
    float* C = (osel >= 0) ? g_proj[osel] : dext;

    const uint32_t smu = smem_u32(dsm);

    const int lr = tid >> 3;
    const int lseg = (tid & 7) * 8;
    size_t gA[4], gB[4];
    uint32_t sOff[4];
    #pragma unroll
    for (int j = 0; j < 4; j++) {
        int r = lr + j * 32;
        gA[j] = (size_t)(by * 128 + r) * DIM + lseg;
        gB[j] = (size_t)(xb * 128 + r) * DIM + lseg;
        sOff[j] = (uint32_t)(r * ROWB + (tid & 7) * 16);
    }

    const int warp_m = (wid >> 2) * 64;
    const int warp_n = (wid & 3) * 32;
    const int quad = lane >> 3, l7 = lane & 7;
    const uint32_t aoff = (uint32_t)((warp_m + (quad & 1) * 8 + l7) * ROWB + (quad >> 1) * 16);
    const uint32_t boff = (uint32_t)((warp_n + (quad >> 1) * 8 + l7) * ROWB + (quad & 1) * 16);

    float acc[4][4][4];
    #pragma unroll
    for (int i = 0; i < 4; i++)
        #pragma unroll
        for (int j = 0; j < 4; j++)
            #pragma unroll
            for (int r = 0; r < 4; r++) acc[i][j][r] = 0.f;

    auto issue_chunk = [&](int c, int stg) {
        const int ko = c << 6;
        const uint32_t sb = smu + stg * STAGEB;
        #pragma unroll
        for (int j = 0; j < 4; j++) {
            asm volatile("cp.async.cg.shared.global [%0], [%1], 16;"
                         :: "r"(sb + sOff[j]), "l"(Ahi + gA[j] + ko));
            asm volatile("cp.async.cg.shared.global [%0], [%1], 16;"
                         :: "r"(sb + TILEB + sOff[j]), "l"(Bhi + gB[j] + ko));
        }
        asm volatile("cp.async.commit_group;");
    };

    issue_chunk(0, 0);
    issue_chunk(1, 1);

    int stg = 0;
    for (int c = 0; c < NC; c++) {
        if (c + 1 < NC) asm volatile("cp.async.wait_group 1;");
        else            asm volatile("cp.async.wait_group 0;");
        __syncthreads();

        if (c + 2 < NC) {
            int nstg = stg + 2; if (nstg >= NSTAGE) nstg -= NSTAGE;
            issue_chunk(c + 2, nstg);
        }

        const uint32_t sb = smu + stg * STAGEB;
        #pragma unroll
        for (int ks = 0; ks < 4; ks++) {
            uint32_t bf[2][4];
            #pragma unroll
            for (int nt = 0; nt < 2; nt++) {
                uint32_t addr = sb + TILEB + boff + nt * (16 * ROWB) + ks * 32;
                asm volatile("ldmatrix.sync.aligned.m8n8.x4.shared.b16 {%0,%1,%2,%3}, [%4];"
                             : "=r"(bf[nt][0]), "=r"(bf[nt][1]), "=r"(bf[nt][2]), "=r"(bf[nt][3])
                             : "r"(addr));
            }
            uint32_t af[4][4];
            #pragma unroll
            for (int mt = 0; mt < 4; mt++) {
                uint32_t addr = sb + aoff + mt * (16 * ROWB) + ks * 32;
                asm volatile("ldmatrix.sync.aligned.m8n8.x4.shared.b16 {%0,%1,%2,%3}, [%4];"
                             : "=r"(af[mt][0]), "=r"(af[mt][1]), "=r"(af[mt][2]), "=r"(af[mt][3])
                             : "r"(addr));
            }
            #pragma unroll
            for (int mt = 0; mt < 4; mt++)
                #pragma unroll
                for (int n8 = 0; n8 < 4; n8++)
                    MMA16816(acc[mt][n8],
                             af[mt][0], af[mt][1], af[mt][2], af[mt][3],
                             bf[n8 >> 1][(n8 & 1) * 2 + 0], bf[n8 >> 1][(n8 & 1) * 2 + 1]);
        }
        stg++; if (stg >= NSTAGE) stg = 0;
    }

    const int erow0 = by * 128 + warp_m + (lane >> 2);
    const int ecol0 = xb * 128 + warp_n + 2 * (lane & 3);
    #pragma unroll
    for (int mt = 0; mt < 4; mt++) {
        #pragma unroll
        for (int n8 = 0; n8 < 4; n8++) {
            const int col = ecol0 + n8 * 8;
            const float bb0 = bias[col], bb1 = bias[col + 1];
            #pragma unroll
            for (int h = 0; h < 2; h++) {
                const int row = erow0 + mt * 16 + h * 8;
                float2 v;
                v.x = acc[mt][n8][2 * h + 0] + bb0;
                v.y = acc[mt][n8][2 * h + 1] + bb1;
                if (do_relu) { v.x = fmaxf(v.x, 0.f); v.y = fmaxf(v.y, 0.f); }
                *(float2*)(C + (size_t)row * DIM + col) = v;
            }
        }
    }
}

// ---------------- tensor-core attention x3 + average ----------------
// Softmax over d without max-subtraction (scores bounded small), exp fused into
// the score-MMA epilogue on the FMA pipe, normalization folded into W-convert.
__global__ __launch_bounds__(128)
void attn_kernel()
{
    __shared__ float Sf[64 * 65];            // exp(scores) [e][d]; reused as o
    __shared__ __half Qt[64 * 24];           // [d][h]
    __shared__ __half Kt[64 * 24];           // [e][h]
    __shared__ uint32_t Vh[16 * 36], Vl[16 * 36];   // half2 rows [h][e2]
    __shared__ uint32_t Wh[64 * 36], Wl[64 * 36];   // half2 rows [d][e2]
    __shared__ float red[128];
    __shared__ float invs[64];

    const int n = blockIdx.x;
    const int t = threadIdx.x;
    const int w = t >> 5;
    const int l = t & 31;
    const int r = l >> 2;
    const int cq = l & 3;

    float oacc[2][4];
    #pragma unroll
    for (int nt = 0; nt < 2; nt++)
        #pragma unroll
        for (int j = 0; j < 4; j++) oacc[nt][j] = 0.f;

    for (int a = 0; a < 3; a++) {
        const float4* Qp = (const float4*)(g_proj[3 * a + 0] + (size_t)n * DIM);
        const float4* Kp = (const float4*)(g_proj[3 * a + 1] + (size_t)n * DIM);
        const float4* Vp = (const float4*)(g_proj[3 * a + 2] + (size_t)n * DIM);

        // stage Q,K transposed fp16; V hi/lo half2
        {
            const int h = t >> 3;
            const int d0 = (t & 7) * 8;
            float4 x0 = Qp[t * 2], x1 = Qp[t * 2 + 1];
            float xs[8] = {x0.x, x0.y, x0.z, x0.w, x1.x, x1.y, x1.z, x1.w};
            #pragma unroll
            for (int j = 0; j < 8; j++) Qt[(d0 + j) * 24 + h] = __float2half_rn(xs[j]);

            float4 k0 = Kp[t * 2], k1 = Kp[t * 2 + 1];
            float ks_[8] = {k0.x, k0.y, k0.z, k0.w, k1.x, k1.y, k1.z, k1.w};
            #pragma unroll
            for (int j = 0; j < 8; j++) Kt[(d0 + j) * 24 + h] = __float2half_rn(ks_[j]);

            float4 v0 = Vp[t * 2], v1 = Vp[t * 2 + 1];
            float vs[8] = {v0.x, v0.y, v0.z, v0.w, v1.x, v1.y, v1.z, v1.w};
            #pragma unroll
            for (int j = 0; j < 4; j++) {
                __half h0 = __float2half_rn(vs[2 * j]);
                __half h1 = __float2half_rn(vs[2 * j + 1]);
                __half2 hv; hv.x = h0; hv.y = h1;
                __half2 lv;
                lv.x = __float2half_rn(vs[2 * j] - __half2float(h0));
                lv.y = __float2half_rn(vs[2 * j + 1] - __half2float(h1));
                Vh[h * 36 + d0 / 2 + j] = *(uint32_t*)&hv;
                Vl[h * 36 + d0 / 2 + j] = *(uint32_t*)&lv;
            }
        }
        __syncthreads();

        // score MMA + fused exp: Sf[e][d] = exp(score/8)
        {
            uint32_t a0 = *(uint32_t*)&Qt[(16 * w + r) * 24 + 2 * cq];
            uint32_t a1 = *(uint32_t*)&Qt[(16 * w + r + 8) * 24 + 2 * cq];
            uint32_t a2 = *(uint32_t*)&Qt[(16 * w + r) * 24 + 2 * cq + 8];
            uint32_t a3 = *(uint32_t*)&Qt[(16 * w + r + 8) * 24 + 2 * cq + 8];
            #pragma unroll
            for (int nt = 0; nt < 8; nt++) {
                const int e0 = nt * 8;
                uint32_t b0 = *(uint32_t*)&Kt[(e0 + r) * 24 + 2 * cq];
                uint32_t b1 = *(uint32_t*)&Kt[(e0 + r) * 24 + 2 * cq + 8];
                float c[4] = {0.f, 0.f, 0.f, 0.f};
                MMA16816(c, a0, a1, a2, a3, b0, b1);
                const int d = 16 * w + r;
                const int e = e0 + 2 * cq;
                Sf[e * 65 + d]            = fast_exp(c[0] * 0.125f);
                Sf[(e + 1) * 65 + d]      = fast_exp(c[1] * 0.125f);
                Sf[e * 65 + d + 8]        = fast_exp(c[2] * 0.125f);
                Sf[(e + 1) * 65 + d + 8]  = fast_exp(c[3] * 0.125f);
            }
        }
        __syncthreads();

        // column sums over d (thread e = t&63, half = t>>6 owns 32 d's)
        {
            const int e = t & 63;
            const int d0 = (t >> 6) * 32;
            float sum = 0.f;
            #pragma unroll 8
            for (int d = 0; d < 32; d++) sum += Sf[e * 65 + d0 + d];
            red[t] = sum;
        }
        __syncthreads();
        if (t < 64) invs[t] = 1.f / (red[t] + red[t + 64]);
        __syncthreads();

        // convert W = exp * inv -> fp16 hi/lo [d][e2]
        for (int idx = t; idx < 2048; idx += 128) {
            const int d = idx >> 5;
            const int e2 = idx & 31;
            float w0 = Sf[(2 * e2) * 65 + d] * invs[2 * e2];
            float w1 = Sf[(2 * e2 + 1) * 65 + d] * invs[2 * e2 + 1];
            __half h0 = __float2half_rn(w0);
            __half h1 = __float2half_rn(w1);
            __half2 hv; hv.x = h0; hv.y = h1;
            __half2 lv;
            lv.x = __float2half_rn(w0 - __half2float(h0));
            lv.y = __float2half_rn(w1 - __half2float(h1));
            Wh[d * 36 + e2] = *(uint32_t*)&hv;
            Wl[d * 36 + e2] = *(uint32_t*)&lv;
        }
        __syncthreads();

        // o = Wh@Vh + Wh@Vl + Wl@Vh
        {
            #pragma unroll
            for (int ks = 0; ks < 4; ks++) {
                uint32_t ah0 = Wh[(16 * w + r) * 36 + 8 * ks + cq];
                uint32_t ah1 = Wh[(16 * w + r + 8) * 36 + 8 * ks + cq];
                uint32_t ah2 = Wh[(16 * w + r) * 36 + 8 * ks + cq + 4];
                uint32_t ah3 = Wh[(16 * w + r + 8) * 36 + 8 * ks + cq + 4];
                uint32_t al0 = Wl[(16 * w + r) * 36 + 8 * ks + cq];
                uint32_t al1 = Wl[(16 * w + r + 8) * 36 + 8 * ks + cq];
                uint32_t al2 = Wl[(16 * w + r) * 36 + 8 * ks + cq + 4];
                uint32_t al3 = Wl[(16 * w + r + 8) * 36 + 8 * ks + cq + 4];
                #pragma unroll
                for (int nt = 0; nt < 2; nt++) {
                    const int h0 = nt * 8;
                    uint32_t vh0 = Vh[(h0 + r) * 36 + 8 * ks + cq];
                    uint32_t vh1 = Vh[(h0 + r) * 36 + 8 * ks + cq + 4];
                    uint32_t vl0 = Vl[(h0 + r) * 36 + 8 * ks + cq];
                    uint32_t vl1 = Vl[(h0 + r) * 36 + 8 * ks + cq + 4];
                    MMA16816(oacc[nt], ah0, ah1, ah2, ah3, vh0, vh1);
                    MMA16816(oacc[nt], ah0, ah1, ah2, ah3, vl0, vl1);
                    MMA16816(oacc[nt], al0, al1, al2, al3, vh0, vh1);
                }
            }
        }
        __syncthreads();
    }

    float* os = Sf;
    {
        #pragma unroll
        for (int nt = 0; nt < 2; nt++) {
            const int h = nt * 8 + 2 * cq;
            const int d = 16 * w + r;
            os[h * 64 + d]           = oacc[nt][0];
            os[(h + 1) * 64 + d]     = oacc[nt][1];
            os[h * 64 + d + 8]       = oacc[nt][2];
            os[(h + 1) * 64 + d + 8] = oacc[nt][3];
        }
    }
    __syncthreads();

    const size_t base = (size_t)n * DIM;
    #pragma unroll
    for (int rr = 0; rr < 8; rr++) {
        const int i = t + rr * 128;
        g_avg_hi[base + i] = __float2half_rn(os[i] * (1.f / 3.f));
    }
}

// ---------------------------------------------------------------------------
extern "C" void kernel_launch(void* const* d_in, const int* in_sizes, int n_in,
                              void* d_out, int out_size)
{
    (void)in_sizes; (void)n_in; (void)out_size;

    cudaFuncSetAttribute(gemm_mma, cudaFuncAttributeMaxDynamicSharedMemorySize, DYN_SMEM);

    {
        const size_t total = 3 * IN2 + 10 * W2;
        const int blocks = (int)((total + 255) / 256);
        decompose_all<<<blocks, 256>>>(
            (const float*)d_in[0], (const float*)d_in[1], (const float*)d_in[2],
            (const float*)d_in[3], (const float*)d_in[5], (const float*)d_in[7],
            (const float*)d_in[9], (const float*)d_in[11], (const float*)d_in[13],
            (const float*)d_in[15], (const float*)d_in[17], (const float*)d_in[19],
            (const float*)d_in[21]);
    }

    // g_w: 0=Wq1 1=Wk1 2=Wv1 3=Wq2 4=Wk2 5=Wv2 6=Wq3 7=Wk3 8=Wv3 9=Wo
    // proj: 0 Q1  1 K1  2 V1  3 Q2  4 K2  5 V2  6 Q3  7 K3  8 V3
    dim3 gproj(24, 128);
    gemm_mma<<<gproj, 256, DYN_SMEM>>>(0,
        0, 5, 7,
        (const float*)d_in[4], (const float*)d_in[14], (const float*)d_in[18],
        0, 5, 7, nullptr, 0);
    gemm_mma<<<gproj, 256, DYN_SMEM>>>(1,
        2, 1, 6,
        (const float*)d_in[8], (const float*)d_in[6], (const float*)d_in[16],
        2, 4, 6, nullptr, 0);
    gemm_mma<<<gproj, 256, DYN_SMEM>>>(2,
        4, 3, 8,
        (const float*)d_in[12], (const float*)d_in[10], (const float*)d_in[20],
        1, 3, 8, nullptr, 0);

    attn_kernel<<<NTOK, 128>>>();

    dim3 gfin(8, 128);
    gemm_mma<<<gfin, 256, DYN_SMEM>>>(3,
        9, 9, 9,
        (const float*)d_in[22], (const float*)d_in[22], (const float*)d_in[22],
        -1, -1, -1, (float*)d_out, 1);
}

// round 11
// speedup vs baseline: 6.3053x; 1.0415x over previous
#include <cuda_runtime.h>
#include <cuda_fp16.h>
#include <cstdint>

#define NTOK 16384
#define DIM  1024
#define NH   16

// ---------------- scratch (allocation-free __device__ globals) ----------------
__device__ float g_proj[9][(size_t)NTOK * DIM];          // fp32 projections
__device__ __half g_in_hi[3][(size_t)NTOK * DIM];        // q,k,v fp16 (row-major)
__device__ __half g_avg_hi[(size_t)NTOK * DIM];          // averaged attn out fp16
__device__ __half g_w_hi[10][(size_t)DIM * DIM];         // weights fp16 (row-major [N,K])

__device__ __forceinline__ uint32_t smem_u32(const void* p) {
    uint32_t a;
    asm("{ .reg .u64 t; cvta.to.shared.u64 t, %1; cvt.u32.u64 %0, t; }" : "=r"(a) : "l"(p));
    return a;
}

#define MMA16816(C, a0, a1, a2, a3, b0, b1)                                          \
    asm volatile("mma.sync.aligned.m16n8k16.row.col.f32.f16.f16.f32 "                \
        "{%0,%1,%2,%3}, {%4,%5,%6,%7}, {%8,%9}, {%0,%1,%2,%3};"                      \
        : "+f"((C)[0]), "+f"((C)[1]), "+f"((C)[2]), "+f"((C)[3])                     \
        : "r"(a0), "r"(a1), "r"(a2), "r"(a3), "r"(b0), "r"(b1))

// FMA-pipe exp: 2^n split via magic number + degree-6 Horner. No MUFU.
__device__ __forceinline__ float fast_exp(float x) {
    float t = fmaf(x, 1.4426950408889634f, 12582912.0f);
    float n = t - 12582912.0f;
    int ni = __float_as_int(t);
    float r = fmaf(n, -0.6931471805599453f, x);
    float p = 1.3888889e-3f;
    p = fmaf(p, r, 8.3333333e-3f);
    p = fmaf(p, r, 4.1666667e-2f);
    p = fmaf(p, r, 1.6666667e-1f);
    p = fmaf(p, r, 0.5f);
    p = fmaf(p, r, 1.0f);
    p = fmaf(p, r, 1.0f);
    int sc = (ni - 0x4B400000 + 127) << 23;
    return p * __int_as_float(sc);
}

// ---------------- fused fp32 -> fp16 convert: all 13 tensors, ONE launch ----------
#define IN2 ((size_t)NTOK * 512)
#define W2  ((size_t)DIM * 512)

__global__ void decompose_all(
    const float* __restrict__ q, const float* __restrict__ k, const float* __restrict__ v,
    const float* __restrict__ w0, const float* __restrict__ w1, const float* __restrict__ w2,
    const float* __restrict__ w3, const float* __restrict__ w4, const float* __restrict__ w5,
    const float* __restrict__ w6, const float* __restrict__ w7, const float* __restrict__ w8,
    const float* __restrict__ w9)
{
    size_t i = (size_t)blockIdx.x * blockDim.x + threadIdx.x;
    const size_t NIN = 3 * IN2;
    const float* src;
    __half* dst;
    size_t off;
    if (i < NIN) {
        int sel = (int)(i / IN2);
        off = (i - (size_t)sel * IN2) * 2;
        src = (sel == 0) ? q : (sel == 1) ? k : v;
        dst = g_in_hi[sel];
    } else {
        size_t j = i - NIN;
        if (j >= 10 * W2) return;
        int sel = (int)(j / W2);
        off = (j - (size_t)sel * W2) * 2;
        const float* ws[10] = {w0, w1, w2, w3, w4, w5, w6, w7, w8, w9};
        src = ws[sel];
        dst = g_w_hi[sel];
    }
    float2 x = *(const float2*)(src + off);
    __half2 hv;
    hv.x = __float2half_rn(x.x);
    hv.y = __float2half_rn(x.y);
    *(__half2*)(dst + off) = hv;
}

// ---------------- fp16 single-pass HMMA GEMM, BK=64, 3-stage (unchanged) ----------
#define ROWB 144
#define TILEB (128 * ROWB)
#define STAGEB (2 * TILEB)
#define NSTAGE 3
#define DYN_SMEM (NSTAGE * STAGEB)
#define NC 16

__global__ __launch_bounds__(256, 2)
void gemm_mma(int a_sel,
              int w0, int w1, int w2,
              const float* __restrict__ b0p, const float* __restrict__ b1p, const float* __restrict__ b2p,
              int o0, int o1, int o2, float* __restrict__ dext, int do_relu)
{
    extern __shared__ __align__(16) char dsm[];

    const int tid = threadIdx.x;
    const int wid = tid >> 5;
    const int lane = tid & 31;
    const int kb = blockIdx.x >> 3;
    const int xb = blockIdx.x & 7;
    const int by = blockIdx.y;

    const __half* Ahi = (a_sel < 3) ? g_in_hi[a_sel] : g_avg_hi;
    const int wsel = (kb == 0) ? w0 : (kb == 1) ? w1 : w2;
    const float* bias = (kb == 0) ? b0p : (kb == 1) ? b1p : b2p;
    const int osel = (kb == 0) ? o0 : (kb == 1) ? o1 : o2;
    const __half* Bhi = g_w_hi[wsel];
    float* C = (osel >= 0) ? g_proj[osel] : dext;

    const uint32_t smu = smem_u32(dsm);

    const int lr = tid >> 3;
    const int lseg = (tid & 7) * 8;
    size_t gA[4], gB[4];
    uint32_t sOff[4];
    #pragma unroll
    for (int j = 0; j < 4; j++) {
        int r = lr + j * 32;
        gA[j] = (size_t)(by * 128 + r) * DIM + lseg;
        gB[j] = (size_t)(xb * 128 + r) * DIM + lseg;
        sOff[j] = (uint32_t)(r * ROWB + (tid & 7) * 16);
    }

    const int warp_m = (wid >> 2) * 64;
    const int warp_n = (wid & 3) * 32;
    const int quad = lane >> 3, l7 = lane & 7;
    const uint32_t aoff = (uint32_t)((warp_m + (quad & 1) * 8 + l7) * ROWB + (quad >> 1) * 16);
    const uint32_t boff = (uint32_t)((warp_n + (quad >> 1) * 8 + l7) * ROWB + (quad & 1) * 16);

    float acc[4][4][4];
    #pragma unroll
    for (int i = 0; i < 4; i++)
        #pragma unroll
        for (int j = 0; j < 4; j++)
            #pragma unroll
            for (int r = 0; r < 4; r++) acc[i][j][r] = 0.f;

    auto issue_chunk = [&](int c, int stg) {
        const int ko = c << 6;
        const uint32_t sb = smu + stg * STAGEB;
        #pragma unroll
        for (int j = 0; j < 4; j++) {
            asm volatile("cp.async.cg.shared.global [%0], [%1], 16;"
                         :: "r"(sb + sOff[j]), "l"(Ahi + gA[j] + ko));
            asm volatile("cp.async.cg.shared.global [%0], [%1], 16;"
                         :: "r"(sb + TILEB + sOff[j]), "l"(Bhi + gB[j] + ko));
        }
        asm volatile("cp.async.commit_group;");
    };

    issue_chunk(0, 0);
    issue_chunk(1, 1);

    int stg = 0;
    for (int c = 0; c < NC; c++) {
        if (c + 1 < NC) asm volatile("cp.async.wait_group 1;");
        else            asm volatile("cp.async.wait_group 0;");
        __syncthreads();

        if (c + 2 < NC) {
            int nstg = stg + 2; if (nstg >= NSTAGE) nstg -= NSTAGE;
            issue_chunk(c + 2, nstg);
        }

        const uint32_t sb = smu + stg * STAGEB;
        #pragma unroll
        for (int ks = 0; ks < 4; ks++) {
            uint32_t bf[2][4];
            #pragma unroll
            for (int nt = 0; nt < 2; nt++) {
                uint32_t addr = sb + TILEB + boff + nt * (16 * ROWB) + ks * 32;
                asm volatile("ldmatrix.sync.aligned.m8n8.x4.shared.b16 {%0,%1,%2,%3}, [%4];"
                             : "=r"(bf[nt][0]), "=r"(bf[nt][1]), "=r"(bf[nt][2]), "=r"(bf[nt][3])
                             : "r"(addr));
            }
            uint32_t af[4][4];
            #pragma unroll
            for (int mt = 0; mt < 4; mt++) {
                uint32_t addr = sb + aoff + mt * (16 * ROWB) + ks * 32;
                asm volatile("ldmatrix.sync.aligned.m8n8.x4.shared.b16 {%0,%1,%2,%3}, [%4];"
                             : "=r"(af[mt][0]), "=r"(af[mt][1]), "=r"(af[mt][2]), "=r"(af[mt][3])
                             : "r"(addr));
            }
            #pragma unroll
            for (int mt = 0; mt < 4; mt++)
                #pragma unroll
                for (int n8 = 0; n8 < 4; n8++)
                    MMA16816(acc[mt][n8],
                             af[mt][0], af[mt][1], af[mt][2], af[mt][3],
                             bf[n8 >> 1][(n8 & 1) * 2 + 0], bf[n8 >> 1][(n8 & 1) * 2 + 1]);
        }
        stg++; if (stg >= NSTAGE) stg = 0;
    }

    const int erow0 = by * 128 + warp_m + (lane >> 2);
    const int ecol0 = xb * 128 + warp_n + 2 * (lane & 3);
    #pragma unroll
    for (int mt = 0; mt < 4; mt++) {
        #pragma unroll
        for (int n8 = 0; n8 < 4; n8++) {
            const int col = ecol0 + n8 * 8;
            const float bb0 = bias[col], bb1 = bias[col + 1];
            #pragma unroll
            for (int h = 0; h < 2; h++) {
                const int row = erow0 + mt * 16 + h * 8;
                float2 v;
                v.x = acc[mt][n8][2 * h + 0] + bb0;
                v.y = acc[mt][n8][2 * h + 1] + bb1;
                if (do_relu) { v.x = fmaxf(v.x, 0.f); v.y = fmaxf(v.y, 0.f); }
                *(float2*)(C + (size_t)row * DIM + col) = v;
            }
        }
    }
}

// ---------------- tensor-core attention x3 + average ----------------
// Single-pass fp16 o-GEMM (o = W_h @ V_h); 34.5 KB smem -> 6 CTA/SM.
__global__ __launch_bounds__(128)
void attn_kernel()
{
    __shared__ float Sf[64 * 65];            // exp(scores) [e][d]; reused as o
    __shared__ __half Qt[64 * 24];           // [d][h]
    __shared__ __half Kt[64 * 24];           // [e][h]
    __shared__ uint32_t Vh[16 * 36];         // half2 rows [h][e2]
    __shared__ uint32_t Wh[64 * 36];         // half2 rows [d][e2]
    __shared__ float invs[64];

    const int n = blockIdx.x;
    const int t = threadIdx.x;
    const int w = t >> 5;
    const int l = t & 31;
    const int r = l >> 2;
    const int cq = l & 3;

    float oacc[2][4];
    #pragma unroll
    for (int nt = 0; nt < 2; nt++)
        #pragma unroll
        for (int j = 0; j < 4; j++) oacc[nt][j] = 0.f;

    for (int a = 0; a < 3; a++) {
        const float4* Qp = (const float4*)(g_proj[3 * a + 0] + (size_t)n * DIM);
        const float4* Kp = (const float4*)(g_proj[3 * a + 1] + (size_t)n * DIM);
        const float4* Vp = (const float4*)(g_proj[3 * a + 2] + (size_t)n * DIM);

        // stage Q,K transposed fp16; V fp16 half2
        {
            const int h = t >> 3;
            const int d0 = (t & 7) * 8;
            float4 x0 = Qp[t * 2], x1 = Qp[t * 2 + 1];
            float xs[8] = {x0.x, x0.y, x0.z, x0.w, x1.x, x1.y, x1.z, x1.w};
            #pragma unroll
            for (int j = 0; j < 8; j++) Qt[(d0 + j) * 24 + h] = __float2half_rn(xs[j]);

            float4 k0 = Kp[t * 2], k1 = Kp[t * 2 + 1];
            float ks_[8] = {k0.x, k0.y, k0.z, k0.w, k1.x, k1.y, k1.z, k1.w};
            #pragma unroll
            for (int j = 0; j < 8; j++) Kt[(d0 + j) * 24 + h] = __float2half_rn(ks_[j]);

            float4 v0 = Vp[t * 2], v1 = Vp[t * 2 + 1];
            float vs[8] = {v0.x, v0.y, v0.z, v0.w, v1.x, v1.y, v1.z, v1.w};
            #pragma unroll
            for (int j = 0; j < 4; j++) {
                __half2 hv;
                hv.x = __float2half_rn(vs[2 * j]);
                hv.y = __float2half_rn(vs[2 * j + 1]);
                Vh[(t >> 3) * 36 + d0 / 2 + j] = *(uint32_t*)&hv;
            }
        }
        __syncthreads();

        // score MMA + fused exp: Sf[e][d] = exp(score/8)
        {
            uint32_t a0 = *(uint32_t*)&Qt[(16 * w + r) * 24 + 2 * cq];
            uint32_t a1 = *(uint32_t*)&Qt[(16 * w + r + 8) * 24 + 2 * cq];
            uint32_t a2 = *(uint32_t*)&Qt[(16 * w + r) * 24 + 2 * cq + 8];
            uint32_t a3 = *(uint32_t*)&Qt[(16 * w + r + 8) * 24 + 2 * cq + 8];
            #pragma unroll
            for (int nt = 0; nt < 8; nt++) {
                const int e0 = nt * 8;
                uint32_t b0 = *(uint32_t*)&Kt[(e0 + r) * 24 + 2 * cq];
                uint32_t b1 = *(uint32_t*)&Kt[(e0 + r) * 24 + 2 * cq + 8];
                float c[4] = {0.f, 0.f, 0.f, 0.f};
                MMA16816(c, a0, a1, a2, a3, b0, b1);
                const int d = 16 * w + r;
                const int e = e0 + 2 * cq;
                Sf[e * 65 + d]            = fast_exp(c[0] * 0.125f);
                Sf[(e + 1) * 65 + d]      = fast_exp(c[1] * 0.125f);
                Sf[e * 65 + d + 8]        = fast_exp(c[2] * 0.125f);
                Sf[(e + 1) * 65 + d + 8]  = fast_exp(c[3] * 0.125f);
            }
        }
        __syncthreads();

        // column sums + reciprocal (threads 0-63, one barrier)
        if (t < 64) {
            float sum = 0.f;
            #pragma unroll 8
            for (int d = 0; d < 64; d++) sum += Sf[t * 65 + d];
            invs[t] = 1.f / sum;
        }
        __syncthreads();

        // W = exp * inv -> fp16 half2 [d][e2]
        for (int idx = t; idx < 2048; idx += 128) {
            const int d = idx >> 5;
            const int e2 = idx & 31;
            __half2 hv;
            hv.x = __float2half_rn(Sf[(2 * e2) * 65 + d] * invs[2 * e2]);
            hv.y = __float2half_rn(Sf[(2 * e2 + 1) * 65 + d] * invs[2 * e2 + 1]);
            Wh[d * 36 + e2] = *(uint32_t*)&hv;
        }
        __syncthreads();

        // o = Wh @ Vh (single pass)
        {
            #pragma unroll
            for (int ks = 0; ks < 4; ks++) {
                uint32_t ah0 = Wh[(16 * w + r) * 36 + 8 * ks + cq];
                uint32_t ah1 = Wh[(16 * w + r + 8) * 36 + 8 * ks + cq];
                uint32_t ah2 = Wh[(16 * w + r) * 36 + 8 * ks + cq + 4];
                uint32_t ah3 = Wh[(16 * w + r + 8) * 36 + 8 * ks + cq + 4];
                #pragma unroll
                for (int nt = 0; nt < 2; nt++) {
                    const int h0 = nt * 8;
                    uint32_t vh0 = Vh[(h0 + r) * 36 + 8 * ks + cq];
                    uint32_t vh1 = Vh[(h0 + r) * 36 + 8 * ks + cq + 4];
                    MMA16816(oacc[nt], ah0, ah1, ah2, ah3, vh0, vh1);
                }
            }
        }
        __syncthreads();
    }

    float* os = Sf;
    {
        #pragma unroll
        for (int nt = 0; nt < 2; nt++) {
            const int h = nt * 8 + 2 * cq;
            const int d = 16 * w + r;
            os[h * 64 + d]           = oacc[nt][0];
            os[(h + 1) * 64 + d]     = oacc[nt][1];
            os[h * 64 + d + 8]       = oacc[nt][2];
            os[(h + 1) * 64 + d + 8] = oacc[nt][3];
        }
    }
    __syncthreads();

    const size_t base = (size_t)n * DIM;
    #pragma unroll
    for (int rr = 0; rr < 8; rr++) {
        const int i = t + rr * 128;
        g_avg_hi[base + i] = __float2half_rn(os[i] * (1.f / 3.f));
    }
}

// ---------------------------------------------------------------------------
extern "C" void kernel_launch(void* const* d_in, const int* in_sizes, int n_in,
                              void* d_out, int out_size)
{
    (void)in_sizes; (void)n_in; (void)out_size;

    cudaFuncSetAttribute(gemm_mma, cudaFuncAttributeMaxDynamicSharedMemorySize, DYN_SMEM);

    {
        const size_t total = 3 * IN2 + 10 * W2;
        const int blocks = (int)((total + 255) / 256);
        decompose_all<<<blocks, 256>>>(
            (const float*)d_in[0], (const float*)d_in[1], (const float*)d_in[2],
            (const float*)d_in[3], (const float*)d_in[5], (const float*)d_in[7],
            (const float*)d_in[9], (const float*)d_in[11], (const float*)d_in[13],
            (const float*)d_in[15], (const float*)d_in[17], (const float*)d_in[19],
            (const float*)d_in[21]);
    }

    // g_w: 0=Wq1 1=Wk1 2=Wv1 3=Wq2 4=Wk2 5=Wv2 6=Wq3 7=Wk3 8=Wv3 9=Wo
    // proj: 0 Q1  1 K1  2 V1  3 Q2  4 K2  5 V2  6 Q3  7 K3  8 V3
    dim3 gproj(24, 128);
    gemm_mma<<<gproj, 256, DYN_SMEM>>>(0,
        0, 5, 7,
        (const float*)d_in[4], (const float*)d_in[14], (const float*)d_in[18],
        0, 5, 7, nullptr, 0);
    gemm_mma<<<gproj, 256, DYN_SMEM>>>(1,
        2, 1, 6,
        (const float*)d_in[8], (const float*)d_in[6], (const float*)d_in[16],
        2, 4, 6, nullptr, 0);
    gemm_mma<<<gproj, 256, DYN_SMEM>>>(2,
        4, 3, 8,
        (const float*)d_in[12], (const float*)d_in[10], (const float*)d_in[20],
        1, 3, 8, nullptr, 0);

    attn_kernel<<<NTOK, 128>>>();

    dim3 gfin(8, 128);
    gemm_mma<<<gfin, 256, DYN_SMEM>>>(3,
        9, 9, 9,
        (const float*)d_in[22], (const float*)d_in[22], (const float*)d_in[22],
        -1, -1, -1, (float*)d_out, 1);
}

// round 12
// speedup vs baseline: 6.6745x; 1.0586x over previous
#include <cuda_runtime.h>
#include <cuda_fp16.h>
#include <cstdint>

#define NTOK 16384
#define DIM  1024
#define NH   16

// ---------------- scratch (allocation-free __device__ globals) ----------------
__device__ __half g_proj[9][(size_t)NTOK * DIM];         // fp16 projections
__device__ __half g_in_hi[3][(size_t)NTOK * DIM];        // q,k,v fp16 (row-major)
__device__ __half g_avg_hi[(size_t)NTOK * DIM];          // averaged attn out fp16
__device__ __half g_w_hi[10][(size_t)DIM * DIM];         // weights fp16 (row-major [N,K])

__device__ __constant__ int c_ws[9] = {0,5,7, 2,1,6, 4,3,8};   // weight sel [a*3+kb]
__device__ __constant__ int c_os[9] = {0,5,7, 2,4,6, 1,3,8};   // proj out sel

__device__ __forceinline__ uint32_t smem_u32(const void* p) {
    uint32_t a;
    asm("{ .reg .u64 t; cvta.to.shared.u64 t, %1; cvt.u32.u64 %0, t; }" : "=r"(a) : "l"(p));
    return a;
}

#define MMA16816(C, a0, a1, a2, a3, b0, b1)                                          \
    asm volatile("mma.sync.aligned.m16n8k16.row.col.f32.f16.f16.f32 "                \
        "{%0,%1,%2,%3}, {%4,%5,%6,%7}, {%8,%9}, {%0,%1,%2,%3};"                      \
        : "+f"((C)[0]), "+f"((C)[1]), "+f"((C)[2]), "+f"((C)[3])                     \
        : "r"(a0), "r"(a1), "r"(a2), "r"(a3), "r"(b0), "r"(b1))

// FMA-pipe exp: 2^n split via magic number + degree-6 Horner. No MUFU.
__device__ __forceinline__ float fast_exp(float x) {
    float t = fmaf(x, 1.4426950408889634f, 12582912.0f);
    float n = t - 12582912.0f;
    int ni = __float_as_int(t);
    float r = fmaf(n, -0.6931471805599453f, x);
    float p = 1.3888889e-3f;
    p = fmaf(p, r, 8.3333333e-3f);
    p = fmaf(p, r, 4.1666667e-2f);
    p = fmaf(p, r, 1.6666667e-1f);
    p = fmaf(p, r, 0.5f);
    p = fmaf(p, r, 1.0f);
    p = fmaf(p, r, 1.0f);
    int sc = (ni - 0x4B400000 + 127) << 23;
    return p * __int_as_float(sc);
}

// ---------------- fused fp32 -> fp16 convert: all 13 tensors, ONE launch ----------
#define IN2 ((size_t)NTOK * 512)
#define W2  ((size_t)DIM * 512)

__global__ void decompose_all(
    const float* __restrict__ q, const float* __restrict__ k, const float* __restrict__ v,
    const float* __restrict__ w0, const float* __restrict__ w1, const float* __restrict__ w2,
    const float* __restrict__ w3, const float* __restrict__ w4, const float* __restrict__ w5,
    const float* __restrict__ w6, const float* __restrict__ w7, const float* __restrict__ w8,
    const float* __restrict__ w9)
{
    size_t i = (size_t)blockIdx.x * blockDim.x + threadIdx.x;
    const size_t NIN = 3 * IN2;
    const float* src;
    __half* dst;
    size_t off;
    if (i < NIN) {
        int sel = (int)(i / IN2);
        off = (i - (size_t)sel * IN2) * 2;
        src = (sel == 0) ? q : (sel == 1) ? k : v;
        dst = g_in_hi[sel];
    } else {
        size_t j = i - NIN;
        if (j >= 10 * W2) return;
        int sel = (int)(j / W2);
        off = (j - (size_t)sel * W2) * 2;
        const float* ws[10] = {w0, w1, w2, w3, w4, w5, w6, w7, w8, w9};
        src = ws[sel];
        dst = g_w_hi[sel];
    }
    float2 x = *(const float2*)(src + off);
    __half2 hv;
    hv.x = __float2half_rn(x.x);
    hv.y = __float2half_rn(x.y);
    *(__half2*)(dst + off) = hv;
}

// ---------------- fp16 single-pass HMMA GEMM, BK=64, 3-stage ----------------
// mode 0: projections, grid (24,128,3) — a = g_in[blockIdx.z], fp16 out to g_proj.
// mode 1: final, grid (8,128,1) — a = g_avg, fp32 out + bias + relu to dext.
#define ROWB 144
#define TILEB (128 * ROWB)
#define STAGEB (2 * TILEB)
#define NSTAGE 3
#define DYN_SMEM (NSTAGE * STAGEB)
#define NC 16

__global__ __launch_bounds__(256, 2)
void gemm_mma(int mode,
              const float* __restrict__ b0, const float* __restrict__ b1, const float* __restrict__ b2,
              const float* __restrict__ b3, const float* __restrict__ b4, const float* __restrict__ b5,
              const float* __restrict__ b6, const float* __restrict__ b7, const float* __restrict__ b8,
              const float* __restrict__ bfin, float* __restrict__ dext)
{
    extern __shared__ __align__(16) char dsm[];

    const int tid = threadIdx.x;
    const int wid = tid >> 5;
    const int lane = tid & 31;
    const int kb = blockIdx.x >> 3;
    const int xb = blockIdx.x & 7;
    const int by = blockIdx.y;
    const int az = blockIdx.z;

    const __half* Ahi;
    const float* bias;
    int wsel, osel;
    if (mode == 0) {
        const int idx = az * 3 + kb;
        wsel = c_ws[idx];
        osel = c_os[idx];
        Ahi = g_in_hi[az];
        bias = (idx == 0) ? b0 : (idx == 1) ? b1 : (idx == 2) ? b2 :
               (idx == 3) ? b3 : (idx == 4) ? b4 : (idx == 5) ? b5 :
               (idx == 6) ? b6 : (idx == 7) ? b7 : b8;
    } else {
        wsel = 9; osel = 0;
        Ahi = g_avg_hi;
        bias = bfin;
    }
    const __half* Bhi = g_w_hi[wsel];

    const uint32_t smu = smem_u32(dsm);

    const int lr = tid >> 3;
    const int lseg = (tid & 7) * 8;
    size_t gA[4], gB[4];
    uint32_t sOff[4];
    #pragma unroll
    for (int j = 0; j < 4; j++) {
        int r = lr + j * 32;
        gA[j] = (size_t)(by * 128 + r) * DIM + lseg;
        gB[j] = (size_t)(xb * 128 + r) * DIM + lseg;
        sOff[j] = (uint32_t)(r * ROWB + (tid & 7) * 16);
    }

    const int warp_m = (wid >> 2) * 64;
    const int warp_n = (wid & 3) * 32;
    const int quad = lane >> 3, l7 = lane & 7;
    const uint32_t aoff = (uint32_t)((warp_m + (quad & 1) * 8 + l7) * ROWB + (quad >> 1) * 16);
    const uint32_t boff = (uint32_t)((warp_n + (quad >> 1) * 8 + l7) * ROWB + (quad & 1) * 16);

    float acc[4][4][4];
    #pragma unroll
    for (int i = 0; i < 4; i++)
        #pragma unroll
        for (int j = 0; j < 4; j++)
            #pragma unroll
            for (int r = 0; r < 4; r++) acc[i][j][r] = 0.f;

    auto issue_chunk = [&](int c, int stg) {
        const int ko = c << 6;
        const uint32_t sb = smu + stg * STAGEB;
        #pragma unroll
        for (int j = 0; j < 4; j++) {
            asm volatile("cp.async.cg.shared.global [%0], [%1], 16;"
                         :: "r"(sb + sOff[j]), "l"(Ahi + gA[j] + ko));
            asm volatile("cp.async.cg.shared.global [%0], [%1], 16;"
                         :: "r"(sb + TILEB + sOff[j]), "l"(Bhi + gB[j] + ko));
        }
        asm volatile("cp.async.commit_group;");
    };

    issue_chunk(0, 0);
    issue_chunk(1, 1);

    int stg = 0;
    for (int c = 0; c < NC; c++) {
        if (c + 1 < NC) asm volatile("cp.async.wait_group 1;");
        else            asm volatile("cp.async.wait_group 0;");
        __syncthreads();

        if (c + 2 < NC) {
            int nstg = stg + 2; if (nstg >= NSTAGE) nstg -= NSTAGE;
            issue_chunk(c + 2, nstg);
        }

        const uint32_t sb = smu + stg * STAGEB;
        #pragma unroll
        for (int ks = 0; ks < 4; ks++) {
            uint32_t bf[2][4];
            #pragma unroll
            for (int nt = 0; nt < 2; nt++) {
                uint32_t addr = sb + TILEB + boff + nt * (16 * ROWB) + ks * 32;
                asm volatile("ldmatrix.sync.aligned.m8n8.x4.shared.b16 {%0,%1,%2,%3}, [%4];"
                             : "=r"(bf[nt][0]), "=r"(bf[nt][1]), "=r"(bf[nt][2]), "=r"(bf[nt][3])
                             : "r"(addr));
            }
            uint32_t af[4][4];
            #pragma unroll
            for (int mt = 0; mt < 4; mt++) {
                uint32_t addr = sb + aoff + mt * (16 * ROWB) + ks * 32;
                asm volatile("ldmatrix.sync.aligned.m8n8.x4.shared.b16 {%0,%1,%2,%3}, [%4];"
                             : "=r"(af[mt][0]), "=r"(af[mt][1]), "=r"(af[mt][2]), "=r"(af[mt][3])
                             : "r"(addr));
            }
            #pragma unroll
            for (int mt = 0; mt < 4; mt++)
                #pragma unroll
                for (int n8 = 0; n8 < 4; n8++)
                    MMA16816(acc[mt][n8],
                             af[mt][0], af[mt][1], af[mt][2], af[mt][3],
                             bf[n8 >> 1][(n8 & 1) * 2 + 0], bf[n8 >> 1][(n8 & 1) * 2 + 1]);
        }
        stg++; if (stg >= NSTAGE) stg = 0;
    }

    // epilogue
    const int erow0 = by * 128 + warp_m + (lane >> 2);
    const int ecol0 = xb * 128 + warp_n + 2 * (lane & 3);
    if (mode == 0) {
        __half* Ch = g_proj[osel];
        #pragma unroll
        for (int mt = 0; mt < 4; mt++) {
            #pragma unroll
            for (int n8 = 0; n8 < 4; n8++) {
                const int col = ecol0 + n8 * 8;
                const float bb0 = bias[col], bb1 = bias[col + 1];
                #pragma unroll
                for (int h = 0; h < 2; h++) {
                    const int row = erow0 + mt * 16 + h * 8;
                    __half2 hv;
                    hv.x = __float2half_rn(acc[mt][n8][2 * h + 0] + bb0);
                    hv.y = __float2half_rn(acc[mt][n8][2 * h + 1] + bb1);
                    *(__half2*)(Ch + (size_t)row * DIM + col) = hv;
                }
            }
        }
    } else {
        #pragma unroll
        for (int mt = 0; mt < 4; mt++) {
            #pragma unroll
            for (int n8 = 0; n8 < 4; n8++) {
                const int col = ecol0 + n8 * 8;
                const float bb0 = bias[col], bb1 = bias[col + 1];
                #pragma unroll
                for (int h = 0; h < 2; h++) {
                    const int row = erow0 + mt * 16 + h * 8;
                    float2 v;
                    v.x = fmaxf(acc[mt][n8][2 * h + 0] + bb0, 0.f);
                    v.y = fmaxf(acc[mt][n8][2 * h + 1] + bb1, 0.f);
                    *(float2*)(dext + (size_t)row * DIM + col) = v;
                }
            }
        }
    }
}

// ---------------- tensor-core attention x3 + average (fp16 projections in) --------
__global__ __launch_bounds__(128)
void attn_kernel()
{
    __shared__ float Sf[64 * 65];            // exp(scores) [e][d]; reused as o
    __shared__ __half Qt[64 * 24];           // [d][h]
    __shared__ __half Kt[64 * 24];           // [e][h]
    __shared__ uint32_t Vh[16 * 36];         // half2 rows [h][e2]
    __shared__ uint32_t Wh[64 * 36];         // half2 rows [d][e2]
    __shared__ float invs[64];

    const int n = blockIdx.x;
    const int t = threadIdx.x;
    const int w = t >> 5;
    const int l = t & 31;
    const int r = l >> 2;
    const int cq = l & 3;

    float oacc[2][4];
    #pragma unroll
    for (int nt = 0; nt < 2; nt++)
        #pragma unroll
        for (int j = 0; j < 4; j++) oacc[nt][j] = 0.f;

    for (int a = 0; a < 3; a++) {
        const uint4* Qp = (const uint4*)(g_proj[3 * a + 0] + (size_t)n * DIM);
        const uint4* Kp = (const uint4*)(g_proj[3 * a + 1] + (size_t)n * DIM);
        const uint4* Vp = (const uint4*)(g_proj[3 * a + 2] + (size_t)n * DIM);

        // stage: thread t covers halves 8t..8t+7 (h = t>>3, d0 = (t&7)*8)
        {
            const int h = t >> 3;
            const int d0 = (t & 7) * 8;

            uint4 qv = Qp[t];
            uint32_t qa[4] = {qv.x, qv.y, qv.z, qv.w};
            #pragma unroll
            for (int j = 0; j < 4; j++) {
                __half2 p = *(__half2*)&qa[j];
                Qt[(d0 + 2 * j) * 24 + h]     = p.x;
                Qt[(d0 + 2 * j + 1) * 24 + h] = p.y;
            }

            uint4 kv = Kp[t];
            uint32_t ka[4] = {kv.x, kv.y, kv.z, kv.w};
            #pragma unroll
            for (int j = 0; j < 4; j++) {
                __half2 p = *(__half2*)&ka[j];
                Kt[(d0 + 2 * j) * 24 + h]     = p.x;
                Kt[(d0 + 2 * j + 1) * 24 + h] = p.y;
            }

            uint4 vv = Vp[t];
            uint32_t va[4] = {vv.x, vv.y, vv.z, vv.w};
            #pragma unroll
            for (int j = 0; j < 4; j++)
                Vh[h * 36 + (d0 >> 1) + j] = va[j];   // pairs already adjacent
        }
        __syncthreads();

        // score MMA + fused exp: Sf[e][d] = exp(score/8)
        {
            uint32_t a0 = *(uint32_t*)&Qt[(16 * w + r) * 24 + 2 * cq];
            uint32_t a1 = *(uint32_t*)&Qt[(16 * w + r + 8) * 24 + 2 * cq];
            uint32_t a2 = *(uint32_t*)&Qt[(16 * w + r) * 24 + 2 * cq + 8];
            uint32_t a3 = *(uint32_t*)&Qt[(16 * w + r + 8) * 24 + 2 * cq + 8];
            #pragma unroll
            for (int nt = 0; nt < 8; nt++) {
                const int e0 = nt * 8;
                uint32_t b0 = *(uint32_t*)&Kt[(e0 + r) * 24 + 2 * cq];
                uint32_t b1 = *(uint32_t*)&Kt[(e0 + r) * 24 + 2 * cq + 8];
                float c[4] = {0.f, 0.f, 0.f, 0.f};
                MMA16816(c, a0, a1, a2, a3, b0, b1);
                const int d = 16 * w + r;
                const int e = e0 + 2 * cq;
                Sf[e * 65 + d]            = fast_exp(c[0] * 0.125f);
                Sf[(e + 1) * 65 + d]      = fast_exp(c[1] * 0.125f);
                Sf[e * 65 + d + 8]        = fast_exp(c[2] * 0.125f);
                Sf[(e + 1) * 65 + d + 8]  = fast_exp(c[3] * 0.125f);
            }
        }
        __syncthreads();

        // column sums + reciprocal (threads 0-63, one barrier)
        if (t < 64) {
            float sum = 0.f;
            #pragma unroll 8
            for (int d = 0; d < 64; d++) sum += Sf[t * 65 + d];
            invs[t] = 1.f / sum;
        }
        __syncthreads();

        // W = exp * inv -> fp16 half2 [d][e2]
        for (int idx = t; idx < 2048; idx += 128) {
            const int d = idx >> 5;
            const int e2 = idx & 31;
            __half2 hv;
            hv.x = __float2half_rn(Sf[(2 * e2) * 65 + d] * invs[2 * e2]);
            hv.y = __float2half_rn(Sf[(2 * e2 + 1) * 65 + d] * invs[2 * e2 + 1]);
            Wh[d * 36 + e2] = *(uint32_t*)&hv;
        }
        __syncthreads();

        // o = Wh @ Vh
        {
            #pragma unroll
            for (int ks = 0; ks < 4; ks++) {
                uint32_t ah0 = Wh[(16 * w + r) * 36 + 8 * ks + cq];
                uint32_t ah1 = Wh[(16 * w + r + 8) * 36 + 8 * ks + cq];
                uint32_t ah2 = Wh[(16 * w + r) * 36 + 8 * ks + cq + 4];
                uint32_t ah3 = Wh[(16 * w + r + 8) * 36 + 8 * ks + cq + 4];
                #pragma unroll
                for (int nt = 0; nt < 2; nt++) {
                    const int h0 = nt * 8;
                    uint32_t vh0 = Vh[(h0 + r) * 36 + 8 * ks + cq];
                    uint32_t vh1 = Vh[(h0 + r) * 36 + 8 * ks + cq + 4];
                    MMA16816(oacc[nt], ah0, ah1, ah2, ah3, vh0, vh1);
                }
            }
        }
        __syncthreads();
    }

    float* os = Sf;
    {
        #pragma unroll
        for (int nt = 0; nt < 2; nt++) {
            const int h = nt * 8 + 2 * cq;
            const int d = 16 * w + r;
            os[h * 64 + d]           = oacc[nt][0];
            os[(h + 1) * 64 + d]     = oacc[nt][1];
            os[h * 64 + d + 8]       = oacc[nt][2];
            os[(h + 1) * 64 + d + 8] = oacc[nt][3];
        }
    }
    __syncthreads();

    const size_t base = (size_t)n * DIM;
    #pragma unroll
    for (int rr = 0; rr < 8; rr++) {
        const int i = t + rr * 128;
        g_avg_hi[base + i] = __float2half_rn(os[i] * (1.f / 3.f));
    }
}

// ---------------------------------------------------------------------------
extern "C" void kernel_launch(void* const* d_in, const int* in_sizes, int n_in,
                              void* d_out, int out_size)
{
    (void)in_sizes; (void)n_in; (void)out_size;

    cudaFuncSetAttribute(gemm_mma, cudaFuncAttributeMaxDynamicSharedMemorySize, DYN_SMEM);

    {
        const size_t total = 3 * IN2 + 10 * W2;
        const int blocks = (int)((total + 255) / 256);
        decompose_all<<<blocks, 256>>>(
            (const float*)d_in[0], (const float*)d_in[1], (const float*)d_in[2],
            (const float*)d_in[3], (const float*)d_in[5], (const float*)d_in[7],
            (const float*)d_in[9], (const float*)d_in[11], (const float*)d_in[13],
            (const float*)d_in[15], (const float*)d_in[17], (const float*)d_in[19],
            (const float*)d_in[21]);
    }

    // one merged projection launch: grid.z = a_sel (query/key/value)
    // bias order (a*3+kb): q:{b4,b14,b18} k:{b8,b6,b16} v:{b12,b10,b20}
    dim3 gproj(24, 128, 3);
    gemm_mma<<<gproj, 256, DYN_SMEM>>>(0,
        (const float*)d_in[4], (const float*)d_in[14], (const float*)d_in[18],
        (const float*)d_in[8], (const float*)d_in[6], (const float*)d_in[16],
        (const float*)d_in[12], (const float*)d_in[10], (const float*)d_in[20],
        nullptr, nullptr);

    attn_kernel<<<NTOK, 128>>>();

    dim3 gfin(8, 128, 1);
    gemm_mma<<<gfin, 256, DYN_SMEM>>>(1,
        nullptr, nullptr, nullptr, nullptr, nullptr, nullptr,
        nullptr, nullptr, nullptr,
        (const float*)d_in[22], (float*)d_out);
}

// round 13
// speedup vs baseline: 6.8570x; 1.0273x over previous
#include <cuda_runtime.h>
#include <cuda_fp16.h>
#include <cstdint>

#define NTOK 16384
#define DIM  1024
#define NH   16

// ---------------- scratch (allocation-free __device__ globals) ----------------
__device__ __half g_proj[9][(size_t)NTOK * DIM];         // fp16 projections
__device__ __half g_in_hi[3][(size_t)NTOK * DIM];        // q,k,v fp16 (row-major)
__device__ __half g_avg_hi[(size_t)NTOK * DIM];          // averaged attn out fp16
__device__ __half g_w_hi[10][(size_t)DIM * DIM];         // weights fp16 (row-major [N,K])

__device__ __constant__ int c_ws[9] = {0,5,7, 2,1,6, 4,3,8};   // weight sel [a*3+kb]
__device__ __constant__ int c_os[9] = {0,5,7, 2,4,6, 1,3,8};   // proj out sel

__device__ __forceinline__ uint32_t smem_u32(const void* p) {
    uint32_t a;
    asm("{ .reg .u64 t; cvta.to.shared.u64 t, %1; cvt.u32.u64 %0, t; }" : "=r"(a) : "l"(p));
    return a;
}

#define MMA16816(C, a0, a1, a2, a3, b0, b1)                                          \
    asm volatile("mma.sync.aligned.m16n8k16.row.col.f32.f16.f16.f32 "                \
        "{%0,%1,%2,%3}, {%4,%5,%6,%7}, {%8,%9}, {%0,%1,%2,%3};"                      \
        : "+f"((C)[0]), "+f"((C)[1]), "+f"((C)[2]), "+f"((C)[3])                     \
        : "r"(a0), "r"(a1), "r"(a2), "r"(a3), "r"(b0), "r"(b1))

// FMA-pipe exp: 2^n split via magic number + degree-6 Horner. No MUFU.
__device__ __forceinline__ float fast_exp(float x) {
    float t = fmaf(x, 1.4426950408889634f, 12582912.0f);
    float n = t - 12582912.0f;
    int ni = __float_as_int(t);
    float r = fmaf(n, -0.6931471805599453f, x);
    float p = 1.3888889e-3f;
    p = fmaf(p, r, 8.3333333e-3f);
    p = fmaf(p, r, 4.1666667e-2f);
    p = fmaf(p, r, 1.6666667e-1f);
    p = fmaf(p, r, 0.5f);
    p = fmaf(p, r, 1.0f);
    p = fmaf(p, r, 1.0f);
    int sc = (ni - 0x4B400000 + 127) << 23;
    return p * __int_as_float(sc);
}

// ---------------- fused fp32 -> fp16 convert: all 13 tensors, ONE launch ----------
#define IN2 ((size_t)NTOK * 512)
#define W2  ((size_t)DIM * 512)

__global__ void decompose_all(
    const float* __restrict__ q, const float* __restrict__ k, const float* __restrict__ v,
    const float* __restrict__ w0, const float* __restrict__ w1, const float* __restrict__ w2,
    const float* __restrict__ w3, const float* __restrict__ w4, const float* __restrict__ w5,
    const float* __restrict__ w6, const float* __restrict__ w7, const float* __restrict__ w8,
    const float* __restrict__ w9)
{
    size_t i = (size_t)blockIdx.x * blockDim.x + threadIdx.x;
    const size_t NIN = 3 * IN2;
    const float* src;
    __half* dst;
    size_t off;
    if (i < NIN) {
        int sel = (int)(i / IN2);
        off = (i - (size_t)sel * IN2) * 2;
        src = (sel == 0) ? q : (sel == 1) ? k : v;
        dst = g_in_hi[sel];
    } else {
        size_t j = i - NIN;
        if (j >= 10 * W2) return;
        int sel = (int)(j / W2);
        off = (j - (size_t)sel * W2) * 2;
        const float* ws[10] = {w0, w1, w2, w3, w4, w5, w6, w7, w8, w9};
        src = ws[sel];
        dst = g_w_hi[sel];
    }
    float2 x = *(const float2*)(src + off);
    __half2 hv;
    hv.x = __float2half_rn(x.x);
    hv.y = __float2half_rn(x.y);
    *(__half2*)(dst + off) = hv;
}

// ---------------- fp16 HMMA GEMM: 128 threads, warp tile 64x64, BK=64, 3-stage ----
// mode 0: projections, grid (24,128,3). mode 1: final, grid (8,128,1).
#define ROWB 144
#define TILEB (128 * ROWB)
#define STAGEB (2 * TILEB)
#define NSTAGE 3
#define DYN_SMEM (NSTAGE * STAGEB)
#define NC 16

__global__ __launch_bounds__(128, 2)
void gemm_mma(int mode,
              const float* __restrict__ b0, const float* __restrict__ b1, const float* __restrict__ b2,
              const float* __restrict__ b3, const float* __restrict__ b4, const float* __restrict__ b5,
              const float* __restrict__ b6, const float* __restrict__ b7, const float* __restrict__ b8,
              const float* __restrict__ bfin, float* __restrict__ dext)
{
    extern __shared__ __align__(16) char dsm[];

    const int tid = threadIdx.x;
    const int wid = tid >> 5;
    const int lane = tid & 31;
    const int kb = blockIdx.x >> 3;
    const int xb = blockIdx.x & 7;
    const int by = blockIdx.y;
    const int az = blockIdx.z;

    const __half* Ahi;
    const float* bias;
    int wsel, osel;
    if (mode == 0) {
        const int idx = az * 3 + kb;
        wsel = c_ws[idx];
        osel = c_os[idx];
        Ahi = g_in_hi[az];
        bias = (idx == 0) ? b0 : (idx == 1) ? b1 : (idx == 2) ? b2 :
               (idx == 3) ? b3 : (idx == 4) ? b4 : (idx == 5) ? b5 :
               (idx == 6) ? b6 : (idx == 7) ? b7 : b8;
    } else {
        wsel = 9; osel = 0;
        Ahi = g_avg_hi;
        bias = bfin;
    }
    const __half* Bhi = g_w_hi[wsel];

    const uint32_t smu = smem_u32(dsm);

    // loader: 1024 16B-segments per tile, 8 per thread.
    // row = (tid>>3) + j*16, seg = tid&7.
    const int lr = tid >> 3;            // 0..15
    const int lseg = (tid & 7) * 8;     // element offset
    size_t gA[8], gB[8];
    uint32_t sOff[8];
    #pragma unroll
    for (int j = 0; j < 8; j++) {
        int r = lr + j * 16;
        gA[j] = (size_t)(by * 128 + r) * DIM + lseg;
        gB[j] = (size_t)(xb * 128 + r) * DIM + lseg;
        sOff[j] = (uint32_t)(r * ROWB + (tid & 7) * 16);
    }

    // warp tiling: 4 warps 2x2, warp tile 64x64
    const int warp_m = (wid >> 1) * 64;
    const int warp_n = (wid & 1) * 64;
    const int quad = lane >> 3, l7 = lane & 7;
    const uint32_t aoff = (uint32_t)((warp_m + (quad & 1) * 8 + l7) * ROWB + (quad >> 1) * 16);
    const uint32_t boff = (uint32_t)((warp_n + (quad >> 1) * 8 + l7) * ROWB + (quad & 1) * 16);

    float acc[4][8][4];
    #pragma unroll
    for (int i = 0; i < 4; i++)
        #pragma unroll
        for (int j = 0; j < 8; j++)
            #pragma unroll
            for (int r = 0; r < 4; r++) acc[i][j][r] = 0.f;

    auto issue_chunk = [&](int c, int stg) {
        const int ko = c << 6;
        const uint32_t sb = smu + stg * STAGEB;
        #pragma unroll
        for (int j = 0; j < 8; j++) {
            asm volatile("cp.async.cg.shared.global [%0], [%1], 16;"
                         :: "r"(sb + sOff[j]), "l"(Ahi + gA[j] + ko));
            asm volatile("cp.async.cg.shared.global [%0], [%1], 16;"
                         :: "r"(sb + TILEB + sOff[j]), "l"(Bhi + gB[j] + ko));
        }
        asm volatile("cp.async.commit_group;");
    };

    issue_chunk(0, 0);
    issue_chunk(1, 1);

    int stg = 0;
    for (int c = 0; c < NC; c++) {
        if (c + 1 < NC) asm volatile("cp.async.wait_group 1;");
        else            asm volatile("cp.async.wait_group 0;");
        __syncthreads();

        if (c + 2 < NC) {
            int nstg = stg + 2; if (nstg >= NSTAGE) nstg -= NSTAGE;
            issue_chunk(c + 2, nstg);
        }

        const uint32_t sb = smu + stg * STAGEB;
        #pragma unroll
        for (int ks = 0; ks < 4; ks++) {
            uint32_t bf[4][4];
            #pragma unroll
            for (int nt = 0; nt < 4; nt++) {
                uint32_t addr = sb + TILEB + boff + nt * (16 * ROWB) + ks * 32;
                asm volatile("ldmatrix.sync.aligned.m8n8.x4.shared.b16 {%0,%1,%2,%3}, [%4];"
                             : "=r"(bf[nt][0]), "=r"(bf[nt][1]), "=r"(bf[nt][2]), "=r"(bf[nt][3])
                             : "r"(addr));
            }
            uint32_t af[4][4];
            #pragma unroll
            for (int mt = 0; mt < 4; mt++) {
                uint32_t addr = sb + aoff + mt * (16 * ROWB) + ks * 32;
                asm volatile("ldmatrix.sync.aligned.m8n8.x4.shared.b16 {%0,%1,%2,%3}, [%4];"
                             : "=r"(af[mt][0]), "=r"(af[mt][1]), "=r"(af[mt][2]), "=r"(af[mt][3])
                             : "r"(addr));
            }
            #pragma unroll
            for (int mt = 0; mt < 4; mt++)
                #pragma unroll
                for (int n8 = 0; n8 < 8; n8++)
                    MMA16816(acc[mt][n8],
                             af[mt][0], af[mt][1], af[mt][2], af[mt][3],
                             bf[n8 >> 1][(n8 & 1) * 2 + 0], bf[n8 >> 1][(n8 & 1) * 2 + 1]);
        }
        stg++; if (stg >= NSTAGE) stg = 0;
    }

    // epilogue
    const int erow0 = by * 128 + warp_m + (lane >> 2);
    const int ecol0 = xb * 128 + warp_n + 2 * (lane & 3);
    if (mode == 0) {
        __half* Ch = g_proj[osel];
        #pragma unroll
        for (int mt = 0; mt < 4; mt++) {
            #pragma unroll
            for (int n8 = 0; n8 < 8; n8++) {
                const int col = ecol0 + n8 * 8;
                const float bb0 = bias[col], bb1 = bias[col + 1];
                #pragma unroll
                for (int h = 0; h < 2; h++) {
                    const int row = erow0 + mt * 16 + h * 8;
                    __half2 hv;
                    hv.x = __float2half_rn(acc[mt][n8][2 * h + 0] + bb0);
                    hv.y = __float2half_rn(acc[mt][n8][2 * h + 1] + bb1);
                    *(__half2*)(Ch + (size_t)row * DIM + col) = hv;
                }
            }
        }
    } else {
        #pragma unroll
        for (int mt = 0; mt < 4; mt++) {
            #pragma unroll
            for (int n8 = 0; n8 < 8; n8++) {
                const int col = ecol0 + n8 * 8;
                const float bb0 = bias[col], bb1 = bias[col + 1];
                #pragma unroll
                for (int h = 0; h < 2; h++) {
                    const int row = erow0 + mt * 16 + h * 8;
                    float2 v;
                    v.x = fmaxf(acc[mt][n8][2 * h + 0] + bb0, 0.f);
                    v.y = fmaxf(acc[mt][n8][2 * h + 1] + bb1, 0.f);
                    *(float2*)(dext + (size_t)row * DIM + col) = v;
                }
            }
        }
    }
}

// ---------------- tensor-core attention x3 + average (unchanged R12) --------------
__global__ __launch_bounds__(128)
void attn_kernel()
{
    __shared__ float Sf[64 * 65];            // exp(scores) [e][d]; reused as o
    __shared__ __half Qt[64 * 24];           // [d][h]
    __shared__ __half Kt[64 * 24];           // [e][h]
    __shared__ uint32_t Vh[16 * 36];         // half2 rows [h][e2]
    __shared__ uint32_t Wh[64 * 36];         // half2 rows [d][e2]
    __shared__ float invs[64];

    const int n = blockIdx.x;
    const int t = threadIdx.x;
    const int w = t >> 5;
    const int l = t & 31;
    const int r = l >> 2;
    const int cq = l & 3;

    float oacc[2][4];
    #pragma unroll
    for (int nt = 0; nt < 2; nt++)
        #pragma unroll
        for (int j = 0; j < 4; j++) oacc[nt][j] = 0.f;

    for (int a = 0; a < 3; a++) {
        const uint4* Qp = (const uint4*)(g_proj[3 * a + 0] + (size_t)n * DIM);
        const uint4* Kp = (const uint4*)(g_proj[3 * a + 1] + (size_t)n * DIM);
        const uint4* Vp = (const uint4*)(g_proj[3 * a + 2] + (size_t)n * DIM);

        {
            const int h = t >> 3;
            const int d0 = (t & 7) * 8;

            uint4 qv = Qp[t];
            uint32_t qa[4] = {qv.x, qv.y, qv.z, qv.w};
            #pragma unroll
            for (int j = 0; j < 4; j++) {
                __half2 p = *(__half2*)&qa[j];
                Qt[(d0 + 2 * j) * 24 + h]     = p.x;
                Qt[(d0 + 2 * j + 1) * 24 + h] = p.y;
            }

            uint4 kv = Kp[t];
            uint32_t ka[4] = {kv.x, kv.y, kv.z, kv.w};
            #pragma unroll
            for (int j = 0; j < 4; j++) {
                __half2 p = *(__half2*)&ka[j];
                Kt[(d0 + 2 * j) * 24 + h]     = p.x;
                Kt[(d0 + 2 * j + 1) * 24 + h] = p.y;
            }

            uint4 vv = Vp[t];
            uint32_t va[4] = {vv.x, vv.y, vv.z, vv.w};
            #pragma unroll
            for (int j = 0; j < 4; j++)
                Vh[h * 36 + (d0 >> 1) + j] = va[j];
        }
        __syncthreads();

        {
            uint32_t a0 = *(uint32_t*)&Qt[(16 * w + r) * 24 + 2 * cq];
            uint32_t a1 = *(uint32_t*)&Qt[(16 * w + r + 8) * 24 + 2 * cq];
            uint32_t a2 = *(uint32_t*)&Qt[(16 * w + r) * 24 + 2 * cq + 8];
            uint32_t a3 = *(uint32_t*)&Qt[(16 * w + r + 8) * 24 + 2 * cq + 8];
            #pragma unroll
            for (int nt = 0; nt < 8; nt++) {
                const int e0 = nt * 8;
                uint32_t b0 = *(uint32_t*)&Kt[(e0 + r) * 24 + 2 * cq];
                uint32_t b1 = *(uint32_t*)&Kt[(e0 + r) * 24 + 2 * cq + 8];
                float c[4] = {0.f, 0.f, 0.f, 0.f};
                MMA16816(c, a0, a1, a2, a3, b0, b1);
                const int d = 16 * w + r;
                const int e = e0 + 2 * cq;
                Sf[e * 65 + d]            = fast_exp(c[0] * 0.125f);
                Sf[(e + 1) * 65 + d]      = fast_exp(c[1] * 0.125f);
                Sf[e * 65 + d + 8]        = fast_exp(c[2] * 0.125f);
                Sf[(e + 1) * 65 + d + 8]  = fast_exp(c[3] * 0.125f);
            }
        }
        __syncthreads();

        if (t < 64) {
            float sum = 0.f;
            #pragma unroll 8
            for (int d = 0; d < 64; d++) sum += Sf[t * 65 + d];
            invs[t] = 1.f / sum;
        }
        __syncthreads();

        for (int idx = t; idx < 2048; idx += 128) {
            const int d = idx >> 5;
            const int e2 = idx & 31;
            __half2 hv;
            hv.x = __float2half_rn(Sf[(2 * e2) * 65 + d] * invs[2 * e2]);
            hv.y = __float2half_rn(Sf[(2 * e2 + 1) * 65 + d] * invs[2 * e2 + 1]);
            Wh[d * 36 + e2] = *(uint32_t*)&hv;
        }
        __syncthreads();

        {
            #pragma unroll
            for (int ks = 0; ks < 4; ks++) {
                uint32_t ah0 = Wh[(16 * w + r) * 36 + 8 * ks + cq];
                uint32_t ah1 = Wh[(16 * w + r + 8) * 36 + 8 * ks + cq];
                uint32_t ah2 = Wh[(16 * w + r) * 36 + 8 * ks + cq + 4];
                uint32_t ah3 = Wh[(16 * w + r + 8) * 36 + 8 * ks + cq + 4];
                #pragma unroll
                for (int nt = 0; nt < 2; nt++) {
                    const int h0 = nt * 8;
                    uint32_t vh0 = Vh[(h0 + r) * 36 + 8 * ks + cq];
                    uint32_t vh1 = Vh[(h0 + r) * 36 + 8 * ks + cq + 4];
                    MMA16816(oacc[nt], ah0, ah1, ah2, ah3, vh0, vh1);
                }
            }
        }
        __syncthreads();
    }

    float* os = Sf;
    {
        #pragma unroll
        for (int nt = 0; nt < 2; nt++) {
            const int h = nt * 8 + 2 * cq;
            const int d = 16 * w + r;
            os[h * 64 + d]           = oacc[nt][0];
            os[(h + 1) * 64 + d]     = oacc[nt][1];
            os[h * 64 + d + 8]       = oacc[nt][2];
            os[(h + 1) * 64 + d + 8] = oacc[nt][3];
        }
    }
    __syncthreads();

    const size_t base = (size_t)n * DIM;
    #pragma unroll
    for (int rr = 0; rr < 8; rr++) {
        const int i = t + rr * 128;
        g_avg_hi[base + i] = __float2half_rn(os[i] * (1.f / 3.f));
    }
}

// ---------------------------------------------------------------------------
extern "C" void kernel_launch(void* const* d_in, const int* in_sizes, int n_in,
                              void* d_out, int out_size)
{
    (void)in_sizes; (void)n_in; (void)out_size;

    cudaFuncSetAttribute(gemm_mma, cudaFuncAttributeMaxDynamicSharedMemorySize, DYN_SMEM);

    {
        const size_t total = 3 * IN2 + 10 * W2;
        const int blocks = (int)((total + 255) / 256);
        decompose_all<<<blocks, 256>>>(
            (const float*)d_in[0], (const float*)d_in[1], (const float*)d_in[2],
            (const float*)d_in[3], (const float*)d_in[5], (const float*)d_in[7],
            (const float*)d_in[9], (const float*)d_in[11], (const float*)d_in[13],
            (const float*)d_in[15], (const float*)d_in[17], (const float*)d_in[19],
            (const float*)d_in[21]);
    }

    // one merged projection launch: grid.z = a_sel (query/key/value)
    dim3 gproj(24, 128, 3);
    gemm_mma<<<gproj, 128, DYN_SMEM>>>(0,
        (const float*)d_in[4], (const float*)d_in[14], (const float*)d_in[18],
        (const float*)d_in[8], (const float*)d_in[6], (const float*)d_in[16],
        (const float*)d_in[12], (const float*)d_in[10], (const float*)d_in[20],
        nullptr, nullptr);

    attn_kernel<<<NTOK, 128>>>();

    dim3 gfin(8, 128, 1);
    gemm_mma<<<gfin, 128, DYN_SMEM>>>(1,
        nullptr, nullptr, nullptr, nullptr, nullptr, nullptr,
        nullptr, nullptr, nullptr,
        (const float*)d_in[22], (float*)d_out);
}

// round 16
// speedup vs baseline: 7.4468x; 1.0860x over previous
#include <cuda_runtime.h>
#include <cuda_fp16.h>
#include <cstdint>

#define NTOK 16384
#define DIM  1024
#define NH   16

// ---------------- scratch (allocation-free __device__ globals) ----------------
__device__ __half g_proj[9][(size_t)NTOK * DIM];         // fp16 projections
__device__ __half g_in_hi[3][(size_t)NTOK * DIM];        // q,k,v fp16 (row-major)
__device__ __half g_avg_hi[(size_t)NTOK * DIM];          // averaged attn out fp16
__device__ __half g_w_hi[10][(size_t)DIM * DIM];         // weights fp16 (row-major [N,K])

__device__ __constant__ int c_ws[9] = {0,5,7, 2,1,6, 4,3,8};   // weight sel [a*3+kb]
__device__ __constant__ int c_os[9] = {0,5,7, 2,4,6, 1,3,8};   // proj out sel

__device__ __forceinline__ uint32_t smem_u32(const void* p) {
    uint32_t a;
    asm("{ .reg .u64 t; cvta.to.shared.u64 t, %1; cvt.u32.u64 %0, t; }" : "=r"(a) : "l"(p));
    return a;
}

#define MMA16816(C, a0, a1, a2, a3, b0, b1)                                          \
    asm volatile("mma.sync.aligned.m16n8k16.row.col.f32.f16.f16.f32 "                \
        "{%0,%1,%2,%3}, {%4,%5,%6,%7}, {%8,%9}, {%0,%1,%2,%3};"                      \
        : "+f"((C)[0]), "+f"((C)[1]), "+f"((C)[2]), "+f"((C)[3])                     \
        : "r"(a0), "r"(a1), "r"(a2), "r"(a3), "r"(b0), "r"(b1))

// pack two f32 -> f16x2 (lo = first arg)
__device__ __forceinline__ uint32_t pack_h2(float lo, float hi) {
    uint32_t d;
    asm("cvt.rn.f16x2.f32 %0, %1, %2;" : "=r"(d) : "f"(hi), "f"(lo));
    return d;
}

// FMA-pipe exp: 2^n split via magic number + degree-6 Horner. No MUFU.
__device__ __forceinline__ float fast_exp(float x) {
    float t = fmaf(x, 1.4426950408889634f, 12582912.0f);
    float n = t - 12582912.0f;
    int ni = __float_as_int(t);
    float r = fmaf(n, -0.6931471805599453f, x);
    float p = 1.3888889e-3f;
    p = fmaf(p, r, 8.3333333e-3f);
    p = fmaf(p, r, 4.1666667e-2f);
    p = fmaf(p, r, 1.6666667e-1f);
    p = fmaf(p, r, 0.5f);
    p = fmaf(p, r, 1.0f);
    p = fmaf(p, r, 1.0f);
    int sc = (ni - 0x4B400000 + 127) << 23;
    return p * __int_as_float(sc);
}

// ---------------- fused fp32 -> fp16 convert: all 13 tensors, ONE launch ----------
#define IN2 ((size_t)NTOK * 512)
#define W2  ((size_t)DIM * 512)

__global__ void decompose_all(
    const float* __restrict__ q, const float* __restrict__ k, const float* __restrict__ v,
    const float* __restrict__ w0, const float* __restrict__ w1, const float* __restrict__ w2,
    const float* __restrict__ w3, const float* __restrict__ w4, const float* __restrict__ w5,
    const float* __restrict__ w6, const float* __restrict__ w7, const float* __restrict__ w8,
    const float* __restrict__ w9)
{
    size_t i = (size_t)blockIdx.x * blockDim.x + threadIdx.x;
    const size_t NIN = 3 * IN2;
    const float* src;
    __half* dst;
    size_t off;
    if (i < NIN) {
        int sel = (int)(i / IN2);
        off = (i - (size_t)sel * IN2) * 2;
        src = (sel == 0) ? q : (sel == 1) ? k : v;
        dst = g_in_hi[sel];
    } else {
        size_t j = i - NIN;
        if (j >= 10 * W2) return;
        int sel = (int)(j / W2);
        off = (j - (size_t)sel * W2) * 2;
        const float* ws[10] = {w0, w1, w2, w3, w4, w5, w6, w7, w8, w9};
        src = ws[sel];
        dst = g_w_hi[sel];
    }
    float2 x = *(const float2*)(src + off);
    __half2 hv;
    hv.x = __float2half_rn(x.x);
    hv.y = __float2half_rn(x.y);
    *(__half2*)(dst + off) = hv;
}

// ---------------- fp16 HMMA GEMM: 128 threads, warp tile 64x64, BK=64, 3-stage ----
#define ROWB 144
#define TILEB (128 * ROWB)
#define STAGEB (2 * TILEB)
#define NSTAGE 3
#define DYN_SMEM (NSTAGE * STAGEB)
#define NC 16

__global__ __launch_bounds__(128, 2)
void gemm_mma(int mode,
              const float* __restrict__ b0, const float* __restrict__ b1, const float* __restrict__ b2,
              const float* __restrict__ b3, const float* __restrict__ b4, const float* __restrict__ b5,
              const float* __restrict__ b6, const float* __restrict__ b7, const float* __restrict__ b8,
              const float* __restrict__ bfin, float* __restrict__ dext)
{
    extern __shared__ __align__(16) char dsm[];

    const int tid = threadIdx.x;
    const int wid = tid >> 5;
    const int lane = tid & 31;
    const int kb = blockIdx.x >> 3;
    const int xb = blockIdx.x & 7;
    const int by = blockIdx.y;
    const int az = blockIdx.z;

    const __half* Ahi;
    const float* bias;
    int wsel, osel;
    if (mode == 0) {
        const int idx = az * 3 + kb;
        wsel = c_ws[idx];
        osel = c_os[idx];
        Ahi = g_in_hi[az];
        bias = (idx == 0) ? b0 : (idx == 1) ? b1 : (idx == 2) ? b2 :
               (idx == 3) ? b3 : (idx == 4) ? b4 : (idx == 5) ? b5 :
               (idx == 6) ? b6 : (idx == 7) ? b7 : b8;
    } else {
        wsel = 9; osel = 0;
        Ahi = g_avg_hi;
        bias = bfin;
    }
    const __half* Bhi = g_w_hi[wsel];

    const uint32_t smu = smem_u32(dsm);

    const int lr = tid >> 3;
    const int lseg = (tid & 7) * 8;
    size_t gA[8], gB[8];
    uint32_t sOff[8];
    #pragma unroll
    for (int j = 0; j < 8; j++) {
        int r = lr + j * 16;
        gA[j] = (size_t)(by * 128 + r) * DIM + lseg;
        gB[j] = (size_t)(xb * 128 + r) * DIM + lseg;
        sOff[j] = (uint32_t)(r * ROWB + (tid & 7) * 16);
    }

    const int warp_m = (wid >> 1) * 64;
    const int warp_n = (wid & 1) * 64;
    const int quad = lane >> 3, l7 = lane & 7;
    const uint32_t aoff = (uint32_t)((warp_m + (quad & 1) * 8 + l7) * ROWB + (quad >> 1) * 16);
    const uint32_t boff = (uint32_t)((warp_n + (quad >> 1) * 8 + l7) * ROWB + (quad & 1) * 16);

    float acc[4][8][4];
    #pragma unroll
    for (int i = 0; i < 4; i++)
        #pragma unroll
        for (int j = 0; j < 8; j++)
            #pragma unroll
            for (int r = 0; r < 4; r++) acc[i][j][r] = 0.f;

    auto issue_chunk = [&](int c, int stg) {
        const int ko = c << 6;
        const uint32_t sb = smu + stg * STAGEB;
        #pragma unroll
        for (int j = 0; j < 8; j++) {
            asm volatile("cp.async.cg.shared.global [%0], [%1], 16;"
                         :: "r"(sb + sOff[j]), "l"(Ahi + gA[j] + ko));
            asm volatile("cp.async.cg.shared.global [%0], [%1], 16;"
                         :: "r"(sb + TILEB + sOff[j]), "l"(Bhi + gB[j] + ko));
        }
        asm volatile("cp.async.commit_group;");
    };

    issue_chunk(0, 0);
    issue_chunk(1, 1);

    int stg = 0;
    for (int c = 0; c < NC; c++) {
        if (c + 1 < NC) asm volatile("cp.async.wait_group 1;");
        else            asm volatile("cp.async.wait_group 0;");
        __syncthreads();

        if (c + 2 < NC) {
            int nstg = stg + 2; if (nstg >= NSTAGE) nstg -= NSTAGE;
            issue_chunk(c + 2, nstg);
        }

        const uint32_t sb = smu + stg * STAGEB;
        #pragma unroll
        for (int ks = 0; ks < 4; ks++) {
            uint32_t bf[4][4];
            #pragma unroll
            for (int nt = 0; nt < 4; nt++) {
                uint32_t addr = sb + TILEB + boff + nt * (16 * ROWB) + ks * 32;
                asm volatile("ldmatrix.sync.aligned.m8n8.x4.shared.b16 {%0,%1,%2,%3}, [%4];"
                             : "=r"(bf[nt][0]), "=r"(bf[nt][1]), "=r"(bf[nt][2]), "=r"(bf[nt][3])
                             : "r"(addr));
            }
            uint32_t af[4][4];
            #pragma unroll
            for (int mt = 0; mt < 4; mt++) {
                uint32_t addr = sb + aoff + mt * (16 * ROWB) + ks * 32;
                asm volatile("ldmatrix.sync.aligned.m8n8.x4.shared.b16 {%0,%1,%2,%3}, [%4];"
                             : "=r"(af[mt][0]), "=r"(af[mt][1]), "=r"(af[mt][2]), "=r"(af[mt][3])
                             : "r"(addr));
            }
            #pragma unroll
            for (int mt = 0; mt < 4; mt++)
                #pragma unroll
                for (int n8 = 0; n8 < 8; n8++)
                    MMA16816(acc[mt][n8],
                             af[mt][0], af[mt][1], af[mt][2], af[mt][3],
                             bf[n8 >> 1][(n8 & 1) * 2 + 0], bf[n8 >> 1][(n8 & 1) * 2 + 1]);
        }
        stg++; if (stg >= NSTAGE) stg = 0;
    }

    const int erow0 = by * 128 + warp_m + (lane >> 2);
    const int ecol0 = xb * 128 + warp_n + 2 * (lane & 3);
    if (mode == 0) {
        __half* Ch = g_proj[osel];
        #pragma unroll
        for (int mt = 0; mt < 4; mt++) {
            #pragma unroll
            for (int n8 = 0; n8 < 8; n8++) {
                const int col = ecol0 + n8 * 8;
                const float bb0 = bias[col], bb1 = bias[col + 1];
                #pragma unroll
                for (int h = 0; h < 2; h++) {
                    const int row = erow0 + mt * 16 + h * 8;
                    __half2 hv;
                    hv.x = __float2half_rn(acc[mt][n8][2 * h + 0] + bb0);
                    hv.y = __float2half_rn(acc[mt][n8][2 * h + 1] + bb1);
                    *(__half2*)(Ch + (size_t)row * DIM + col) = hv;
                }
            }
        }
    } else {
        #pragma unroll
        for (int mt = 0; mt < 4; mt++) {
            #pragma unroll
            for (int n8 = 0; n8 < 8; n8++) {
                const int col = ecol0 + n8 * 8;
                const float bb0 = bias[col], bb1 = bias[col + 1];
                #pragma unroll
                for (int h = 0; h < 2; h++) {
                    const int row = erow0 + mt * 16 + h * 8;
                    float2 v;
                    v.x = fmaxf(acc[mt][n8][2 * h + 0] + bb0, 0.f);
                    v.y = fmaxf(acc[mt][n8][2 * h + 1] + bb1, 0.f);
                    *(float2*)(dext + (size_t)row * DIM + col) = v;
                }
            }
        }
    }
}

// ---------------- tensor-core attention: in-register softmax ----------------
// Warp w owns S rows d in [16w,16w+16). exp on fragments; column sums via
// shfl_xor + cross-warp Psum table; normalize+pack C-frag -> A-frag in regs.
#define SM_QT   0                      // 64*24 half = 3072 B
#define SM_KT   3072                   // 64*24 half = 3072 B
#define SM_VH   6144                   // 16*36 u32  = 2304 B
#define SM_PS   8448                   // 64*5 float = 1280 B
#define SM_INV  9728                   // 64 float   = 256 B
#define SM_ATTN 9984                   // osh (16*64 half = 2048 B) overlaps Qt

__global__ __launch_bounds__(128)
void attn_kernel()
{
    __shared__ __align__(16) unsigned char smb[SM_ATTN];
    __half*   Qt   = (__half*)(smb + SM_QT);
    __half*   Kt   = (__half*)(smb + SM_KT);
    uint32_t* Vh   = (uint32_t*)(smb + SM_VH);
    float*    Psum = (float*)(smb + SM_PS);
    float*    invs = (float*)(smb + SM_INV);

    const int n = blockIdx.x;
    const int t = threadIdx.x;
    const int w = t >> 5;
    const int l = t & 31;
    const int r = l >> 2;       // group id (row within 16-tile)
    const int cq = l & 3;       // thread-in-group

    float oacc[2][4];
    #pragma unroll
    for (int nt = 0; nt < 2; nt++)
        #pragma unroll
        for (int j = 0; j < 4; j++) oacc[nt][j] = 0.f;

    for (int a = 0; a < 3; a++) {
        const uint4* Qp = (const uint4*)(g_proj[3 * a + 0] + (size_t)n * DIM);
        const uint4* Kp = (const uint4*)(g_proj[3 * a + 1] + (size_t)n * DIM);
        const uint4* Vp = (const uint4*)(g_proj[3 * a + 2] + (size_t)n * DIM);

        // stage: thread t covers halves 8t..8t+7 (h = t>>3, d0 = (t&7)*8)
        {
            const int h = t >> 3;
            const int d0 = (t & 7) * 8;

            uint4 qv = Qp[t];
            uint32_t qa[4] = {qv.x, qv.y, qv.z, qv.w};
            #pragma unroll
            for (int j = 0; j < 4; j++) {
                __half2 p = *(__half2*)&qa[j];
                Qt[(d0 + 2 * j) * 24 + h]     = p.x;
                Qt[(d0 + 2 * j + 1) * 24 + h] = p.y;
            }

            uint4 kv = Kp[t];
            uint32_t ka[4] = {kv.x, kv.y, kv.z, kv.w};
            #pragma unroll
            for (int j = 0; j < 4; j++) {
                __half2 p = *(__half2*)&ka[j];
                Kt[(d0 + 2 * j) * 24 + h]     = p.x;
                Kt[(d0 + 2 * j + 1) * 24 + h] = p.y;
            }

            uint4 vv = Vp[t];
            uint32_t va[4] = {vv.x, vv.y, vv.z, vv.w};
            #pragma unroll
            for (int j = 0; j < 4; j++)
                Vh[h * 36 + (d0 >> 1) + j] = va[j];
        }
        __syncthreads();

        // score MMA + exp on fragments
        float sc[8][4];
        {
            uint32_t a0 = *(uint32_t*)&Qt[(16 * w + r) * 24 + 2 * cq];
            uint32_t a1 = *(uint32_t*)&Qt[(16 * w + r + 8) * 24 + 2 * cq];
            uint32_t a2 = *(uint32_t*)&Qt[(16 * w + r) * 24 + 2 * cq + 8];
            uint32_t a3 = *(uint32_t*)&Qt[(16 * w + r + 8) * 24 + 2 * cq + 8];
            #pragma unroll
            for (int nt = 0; nt < 8; nt++) {
                const int e0 = nt * 8;
                uint32_t b0 = *(uint32_t*)&Kt[(e0 + r) * 24 + 2 * cq];
                uint32_t b1 = *(uint32_t*)&Kt[(e0 + r) * 24 + 2 * cq + 8];
                float c[4] = {0.f, 0.f, 0.f, 0.f};
                MMA16816(c, a0, a1, a2, a3, b0, b1);
                sc[nt][0] = fast_exp(c[0] * 0.125f);
                sc[nt][1] = fast_exp(c[1] * 0.125f);
                sc[nt][2] = fast_exp(c[2] * 0.125f);
                sc[nt][3] = fast_exp(c[3] * 0.125f);
            }
        }

        // per-warp column partials: reduce over r (masks 4,8,16), write Psum[e][w]
        #pragma unroll
        for (int nt = 0; nt < 8; nt++) {
            float p0 = sc[nt][0] + sc[nt][2];
            float p1 = sc[nt][1] + sc[nt][3];
            p0 += __shfl_xor_sync(0xFFFFFFFF, p0, 4);
            p1 += __shfl_xor_sync(0xFFFFFFFF, p1, 4);
            p0 += __shfl_xor_sync(0xFFFFFFFF, p0, 8);
            p1 += __shfl_xor_sync(0xFFFFFFFF, p1, 8);
            p0 += __shfl_xor_sync(0xFFFFFFFF, p0, 16);
            p1 += __shfl_xor_sync(0xFFFFFFFF, p1, 16);
            if (r == 0) {
                const int e = nt * 8 + 2 * cq;
                Psum[e * 5 + w]       = p0;
                Psum[(e + 1) * 5 + w] = p1;
            }
        }
        __syncthreads();

        if (t < 64)
            invs[t] = 1.f / (Psum[t * 5 + 0] + Psum[t * 5 + 1] +
                             Psum[t * 5 + 2] + Psum[t * 5 + 3]);
        __syncthreads();

        // normalize + pack C-frag -> A-frag (identity layout), then o-MMA
        uint32_t wlo[8], whi[8];
        #pragma unroll
        for (int nt = 0; nt < 8; nt++) {
            const int e = nt * 8 + 2 * cq;
            const float iv0 = invs[e], iv1 = invs[e + 1];
            wlo[nt] = pack_h2(sc[nt][0] * iv0, sc[nt][1] * iv1);
            whi[nt] = pack_h2(sc[nt][2] * iv0, sc[nt][3] * iv1);
        }
        #pragma unroll
        for (int ks = 0; ks < 4; ks++) {
            #pragma unroll
            for (int nt = 0; nt < 2; nt++) {
                const int h0 = nt * 8;
                uint32_t vh0 = Vh[(h0 + r) * 36 + 8 * ks + cq];
                uint32_t vh1 = Vh[(h0 + r) * 36 + 8 * ks + cq + 4];
                MMA16816(oacc[nt], wlo[2 * ks], whi[2 * ks],
                         wlo[2 * ks + 1], whi[2 * ks + 1], vh0, vh1);
            }
        }
        __syncthreads();   // before next-iter staging overwrites Qt/Kt/Vh/Psum
    }

    // write o fragments to smem (16 heads x 64 d = 2048 B), then one uint4 row copy
    __half* osh = (__half*)smb;
    {
        #pragma unroll
        for (int nt = 0; nt < 2; nt++) {
            const int h = nt * 8 + 2 * cq;
            const int d = 16 * w + r;
            osh[h * 64 + d]           = __float2half_rn(oacc[nt][0] * (1.f / 3.f));
            osh[(h + 1) * 64 + d]     = __float2half_rn(oacc[nt][1] * (1.f / 3.f));
            osh[h * 64 + d + 8]       = __float2half_rn(oacc[nt][2] * (1.f / 3.f));
            osh[(h + 1) * 64 + d + 8] = __float2half_rn(oacc[nt][3] * (1.f / 3.f));
        }
    }
    __syncthreads();

    // one row = 1024 halves = 128 uint4 — exactly one per thread
    uint4* dst = (uint4*)(g_avg_hi + (size_t)n * DIM);
    const uint4* srcv = (const uint4*)osh;
    dst[t] = srcv[t];
}

// ---------------------------------------------------------------------------
extern "C" void kernel_launch(void* const* d_in, const int* in_sizes, int n_in,
                              void* d_out, int out_size)
{
    (void)in_sizes; (void)n_in; (void)out_size;

    cudaFuncSetAttribute(gemm_mma, cudaFuncAttributeMaxDynamicSharedMemorySize, DYN_SMEM);

    {
        const size_t total = 3 * IN2 + 10 * W2;
        const int blocks = (int)((total + 255) / 256);
        decompose_all<<<blocks, 256>>>(
            (const float*)d_in[0], (const float*)d_in[1], (const float*)d_in[2],
            (const float*)d_in[3], (const float*)d_in[5], (const float*)d_in[7],
            (const float*)d_in[9], (const float*)d_in[11], (const float*)d_in[13],
            (const float*)d_in[15], (const float*)d_in[17], (const float*)d_in[19],
            (const float*)d_in[21]);
    }

    dim3 gproj(24, 128, 3);
    gemm_mma<<<gproj, 128, DYN_SMEM>>>(0,
        (const float*)d_in[4], (const float*)d_in[14], (const float*)d_in[18],
        (const float*)d_in[8], (const float*)d_in[6], (const float*)d_in[16],
        (const float*)d_in[12], (const float*)d_in[10], (const float*)d_in[20],
        nullptr, nullptr);

    attn_kernel<<<NTOK, 128>>>();

    dim3 gfin(8, 128, 1);
    gemm_mma<<<gfin, 128, DYN_SMEM>>>(1,
        nullptr, nullptr, nullptr, nullptr, nullptr, nullptr,
        nullptr, nullptr, nullptr,
        (const float*)d_in[22], (float*)d_out);
}